// round 1
// baseline (speedup 1.0000x reference)
#include <cuda_runtime.h>
#include <math.h>
#include <float.h>

#define NGENE 50000
#define NDIS  25000
#define E1N   150000
#define E2N   150000
#define CDIM  128
#define HC    512   /* H_HEADS * C_HID */

// ---------------- scratch (static __device__ — no allocation) ----------------
__device__ float g_Hg[NGENE*CDIM];
__device__ float g_Hd[NDIS*CDIM];
__device__ float g_gene[NGENE*CDIM];
__device__ float g_xs[NGENE*HC];
__device__ float g_xd[NGENE*HC];
__device__ float g_ls[NGENE*4];
__device__ float g_ld[NGENE*4];
__device__ float g_s1[CDIM];
__device__ float g_s2[CDIM];
__device__ float g_scale[CDIM];
__device__ float g_shift[CDIM];
__device__ int   g_cnt[NGENE];
__device__ int   g_rowptr[NGENE+1];
__device__ int   g_wptr[NGENE];
__device__ int   g_elist[E2N+NGENE];

// ---------------- utility kernels ----------------
__global__ void zero_f(float* p, int n){ int i = blockIdx.x*blockDim.x+threadIdx.x; if(i<n) p[i]=0.f; }
__global__ void zero_i(int* p, int n){ int i = blockIdx.x*blockDim.x+threadIdx.x; if(i<n) p[i]=0; }

// ---------------- SGEMM: C[M,N] = A[M,K] @ B[K,N] (+bias, relu if FUSED) ----------------
// BM=128, BN=128, BK=8, 256 threads, 8x8 per-thread tile.
template<int FUSED>
__global__ __launch_bounds__(256)
void sgemm(const float* __restrict__ A, const float* __restrict__ B,
           const float* __restrict__ bias, float* __restrict__ C,
           int M, int N, int K)
{
    __shared__ float As[8][128];
    __shared__ float Bs[8][128];

    int t  = threadIdx.x;
    int tx = t & 15, ty = t >> 4;
    int m0 = blockIdx.y * 128, n0 = blockIdx.x * 128;

    int arow = t >> 1,  acol = (t & 1) * 4;
    int brow = t >> 5,  bcol = (t & 31) * 4;

    const float* Aptr = A + (size_t)(m0 + arow) * K + acol;
    const float* Bptr = B + (size_t)brow * N + n0 + bcol;
    bool aval = (m0 + arow) < M;

    float acc[8][8];
    #pragma unroll
    for (int i=0;i<8;i++)
        #pragma unroll
        for (int j=0;j<8;j++) acc[i][j]=0.f;

    for (int k0 = 0; k0 < K; k0 += 8) {
        float4 av = aval ? *(const float4*)(Aptr + k0) : make_float4(0.f,0.f,0.f,0.f);
        float4 bv = *(const float4*)(Bptr + (size_t)k0 * N);

        As[acol+0][arow]=av.x; As[acol+1][arow]=av.y;
        As[acol+2][arow]=av.z; As[acol+3][arow]=av.w;
        *(float4*)&Bs[brow][bcol] = bv;
        __syncthreads();

        #pragma unroll
        for (int kk = 0; kk < 8; kk++) {
            float4 a0 = *(const float4*)&As[kk][ty*8];
            float4 a1 = *(const float4*)&As[kk][ty*8+4];
            float4 b0 = *(const float4*)&Bs[kk][tx*8];
            float4 b1 = *(const float4*)&Bs[kk][tx*8+4];
            float fa[8] = {a0.x,a0.y,a0.z,a0.w,a1.x,a1.y,a1.z,a1.w};
            float fb[8] = {b0.x,b0.y,b0.z,b0.w,b1.x,b1.y,b1.z,b1.w};
            #pragma unroll
            for (int i=0;i<8;i++)
                #pragma unroll
                for (int j=0;j<8;j++)
                    acc[i][j] += fa[i]*fb[j];
        }
        __syncthreads();
    }

    #pragma unroll
    for (int i=0;i<8;i++) {
        int r = m0 + ty*8 + i;
        if (r < M) {
            #pragma unroll
            for (int j=0;j<8;j++) {
                int col = n0 + tx*8 + j;
                float v = acc[i][j];
                if (FUSED) { v += bias[col]; v = fmaxf(v, 0.f); }
                C[(size_t)r*N + col] = v;
            }
        }
    }
}

// ---------------- BatchNorm stats (N=128 columns, row-major H) ----------------
__global__ __launch_bounds__(256)
void col_stats(const float* __restrict__ H, int M, float* s1, float* s2)
{
    int c = threadIdx.x & 127;
    int rhalf = threadIdx.x >> 7;
    float a = 0.f, b = 0.f;
    for (int r = blockIdx.x*2 + rhalf; r < M; r += gridDim.x*2) {
        float v = H[(size_t)r*128 + c];
        a += v; b += v*v;
    }
    __shared__ float sa[256], sb[256];
    sa[threadIdx.x]=a; sb[threadIdx.x]=b;
    __syncthreads();
    if (threadIdx.x < 128) {
        atomicAdd(&s1[c], sa[threadIdx.x]+sa[threadIdx.x+128]);
        atomicAdd(&s2[c], sb[threadIdx.x]+sb[threadIdx.x+128]);
    }
}

__global__ void bn_finalize(const float* s1, const float* s2,
                            const float* g, const float* beta,
                            float M, float* scale, float* shift)
{
    int c = threadIdx.x;  // 128
    float mu  = s1[c] / M;
    float var = s2[c] / M - mu*mu;
    float inv = rsqrtf(var + 1e-5f);
    scale[c] = g[c]*inv;
    shift[c] = beta[c] - mu*g[c]*inv;
}

__global__ void bn_apply(const float* __restrict__ H, const float* __restrict__ scale,
                         const float* __restrict__ shift, float* __restrict__ out, int n)
{
    int i = blockIdx.x*blockDim.x + threadIdx.x;
    if (i < n) { int c = i & 127; out[i] = H[i]*scale[c] + shift[c]; }
}

// ---------------- attention scores: l[n,h] = sum_c x[n,h,c]*a[h,c] ----------------
__global__ __launch_bounds__(128)
void att_scores(const float* __restrict__ x, const float* __restrict__ a,
                float* __restrict__ lout)
{
    int n = blockIdx.x; int c = threadIdx.x;
    const float* xr = x + (size_t)n*512;
    float v0 = xr[c]      * a[c];
    float v1 = xr[128+c]  * a[128+c];
    float v2 = xr[256+c]  * a[256+c];
    float v3 = xr[384+c]  * a[384+c];
    #pragma unroll
    for (int off=16; off; off>>=1) {
        v0 += __shfl_down_sync(0xffffffff, v0, off);
        v1 += __shfl_down_sync(0xffffffff, v1, off);
        v2 += __shfl_down_sync(0xffffffff, v2, off);
        v3 += __shfl_down_sync(0xffffffff, v3, off);
    }
    __shared__ float par[4][4];
    int warp = c >> 5, lane = c & 31;
    if (!lane) { par[0][warp]=v0; par[1][warp]=v1; par[2][warp]=v2; par[3][warp]=v3; }
    __syncthreads();
    if (c < 4) lout[(size_t)n*4 + c] = par[c][0]+par[c][1]+par[c][2]+par[c][3];
}

// ---------------- CSR build over destination nodes ----------------
// PyG semantics: original edges kept iff src!=dst (numeric), then self-loops 0..nloop-1.
__global__ void edge_count(const int* __restrict__ src, const int* __restrict__ dst,
                           int E, int nloop, int* cnt)
{
    int i = blockIdx.x*blockDim.x + threadIdx.x;
    if (i >= E + nloop) return;
    int d;
    if (i < E) { int s = src[i]; d = dst[i]; if (s == d) return; }
    else d = i - E;
    atomicAdd(&cnt[d], 1);
}

__global__ void edge_scatter(const int* __restrict__ src, const int* __restrict__ dst,
                             int E, int nloop, int* wptr, int* elist)
{
    int i = blockIdx.x*blockDim.x + threadIdx.x;
    if (i >= E + nloop) return;
    int s, d;
    if (i < E) { s = src[i]; d = dst[i]; if (s == d) return; }
    else { d = i - E; s = d; }
    int pos = atomicAdd(&wptr[d], 1);
    elist[pos] = s;
}

// single-block exclusive scan of cnt[0..n) -> rowptr[0..n], copy to wptr
__global__ __launch_bounds__(1024)
void exscan(const int* __restrict__ cnt, int* __restrict__ rowptr,
            int* __restrict__ wptr, int n)
{
    __shared__ int sums[1024];
    int t = threadIdx.x;
    int chunk = (n + 1023) >> 10;
    int b = t*chunk, e = min(n, b+chunk);
    int s = 0;
    for (int i=b; i<e; i++) s += cnt[i];
    sums[t] = s;
    __syncthreads();
    for (int off=1; off<1024; off<<=1) {
        int v = (t >= off) ? sums[t-off] : 0;
        __syncthreads();
        sums[t] += v;
        __syncthreads();
    }
    int base = (t==0) ? 0 : sums[t-1];
    for (int i=b; i<e; i++) { rowptr[i]=base; wptr[i]=base; base += cnt[i]; }
    if (t == 1023) rowptr[n] = sums[1023];
}

// ---------------- per-dst softmax + gather aggregation ----------------
// out[d,c] = base[d,c] + mean_h( sum_e alpha[e,h]*xs[src_e,h,c] ) + bias[c]
__global__ __launch_bounds__(128)
void gat_aggregate(const float* __restrict__ xs, const float* __restrict__ ls,
                   const float* __restrict__ ld,
                   const int* __restrict__ rowptr, const int* __restrict__ elist,
                   const float* __restrict__ base, const float* __restrict__ bias,
                   float* __restrict__ out)
{
    int d = blockIdx.x;
    int c = threadIdx.x;  // 128 threads = channel
    int e0 = rowptr[d], e1 = rowptr[d+1];

    __shared__ float sm[4], sdinv[4], sldv[4];
    __shared__ float w[128*4];
    __shared__ int   ssrc[128];

    if (c < 4) {
        float ldh = ld[(size_t)d*4 + c];
        sldv[c] = ldh;
        float mx = -3.0e38f;
        for (int e=e0; e<e1; e++) {
            int s = elist[e];
            float x = ls[(size_t)s*4 + c] + ldh;
            x = (x > 0.f) ? x : 0.2f*x;
            mx = fmaxf(mx, x);
        }
        float den = 0.f;
        for (int e=e0; e<e1; e++) {
            int s = elist[e];
            float x = ls[(size_t)s*4 + c] + ldh;
            x = (x > 0.f) ? x : 0.2f*x;
            den += __expf(x - mx);
        }
        sm[c] = mx;
        sdinv[c] = (e1 > e0) ? (1.f/den) : 0.f;
    }
    __syncthreads();

    float a0=0.f, a1=0.f, a2=0.f, a3=0.f;
    for (int eb=e0; eb<e1; eb+=128) {
        int ne = min(128, e1-eb);
        if (c < ne) ssrc[c] = elist[eb + c];
        __syncthreads();
        for (int t=c; t < ne*4; t += 128) {
            int e = t >> 2, h = t & 3;
            int s = ssrc[e];
            float x = ls[(size_t)s*4 + h] + sldv[h];
            x = (x > 0.f) ? x : 0.2f*x;
            w[t] = __expf(x - sm[h]) * sdinv[h];
        }
        __syncthreads();
        for (int e=0; e<ne; e++) {
            const float* xr = xs + (size_t)ssrc[e]*512;
            float4 ww = *(const float4*)&w[e*4];
            a0 += ww.x * xr[c];
            a1 += ww.y * xr[128+c];
            a2 += ww.z * xr[256+c];
            a3 += ww.w * xr[384+c];
        }
        __syncthreads();
    }
    size_t oi = (size_t)d*128 + c;
    out[oi] = base[oi] + 0.25f*(a0+a1+a2+a3) + bias[c];
}

// ---------------- launch ----------------
extern "C" void kernel_launch(void* const* d_in, const int* in_sizes, int n_in,
                              void* d_out, int out_size)
{
    const float* x_gene = (const float*)d_in[0];
    const float* x_dis  = (const float*)d_in[1];
    const int*   e1s    = (const int*)d_in[2];
    const int*   e1d    = (const int*)d_in[3];
    const int*   e2s    = (const int*)d_in[4];
    const int*   e2d    = (const int*)d_in[5];
    const float* Wg    = (const float*)d_in[6];
    const float* bg    = (const float*)d_in[7];
    const float* gg    = (const float*)d_in[8];
    const float* betag = (const float*)d_in[9];
    const float* Wd    = (const float*)d_in[10];
    const float* bd    = (const float*)d_in[11];
    const float* gd    = (const float*)d_in[12];
    const float* betad = (const float*)d_in[13];
    const float* W1s = (const float*)d_in[14];
    const float* W1d = (const float*)d_in[15];
    const float* a1s = (const float*)d_in[16];
    const float* a1d = (const float*)d_in[17];
    const float* b1  = (const float*)d_in[18];
    const float* W2s = (const float*)d_in[19];
    const float* W2d = (const float*)d_in[20];
    const float* a2s = (const float*)d_in[21];
    const float* a2d = (const float*)d_in[22];
    const float* b2  = (const float*)d_in[23];

    float *Hg,*Hd,*gene,*xs,*xd,*ls,*ld,*s1,*s2,*scale,*shift;
    int *cnt,*rowptr,*wptr,*elist;
    cudaGetSymbolAddress((void**)&Hg,    g_Hg);
    cudaGetSymbolAddress((void**)&Hd,    g_Hd);
    cudaGetSymbolAddress((void**)&gene,  g_gene);
    cudaGetSymbolAddress((void**)&xs,    g_xs);
    cudaGetSymbolAddress((void**)&xd,    g_xd);
    cudaGetSymbolAddress((void**)&ls,    g_ls);
    cudaGetSymbolAddress((void**)&ld,    g_ld);
    cudaGetSymbolAddress((void**)&s1,    g_s1);
    cudaGetSymbolAddress((void**)&s2,    g_s2);
    cudaGetSymbolAddress((void**)&scale, g_scale);
    cudaGetSymbolAddress((void**)&shift, g_shift);
    cudaGetSymbolAddress((void**)&cnt,   g_cnt);
    cudaGetSymbolAddress((void**)&rowptr,g_rowptr);
    cudaGetSymbolAddress((void**)&wptr,  g_wptr);
    cudaGetSymbolAddress((void**)&elist, g_elist);

    float* out_gene = (float*)d_out;
    float* out_dis  = (float*)d_out + (size_t)NGENE*CDIM;

    // ---- encoders: h = relu(x@W + b) ----
    sgemm<1><<<dim3(1, (NGENE+127)/128), 256>>>(x_gene, Wg, bg, Hg, NGENE, 128, 512);
    sgemm<1><<<dim3(1, (NDIS +127)/128), 256>>>(x_dis,  Wd, bd, Hd, NDIS,  128, 256);

    // BN gene
    zero_f<<<1,128>>>(s1, CDIM);
    zero_f<<<1,128>>>(s2, CDIM);
    col_stats<<<256,256>>>(Hg, NGENE, s1, s2);
    bn_finalize<<<1,128>>>(s1, s2, gg, betag, (float)NGENE, scale, shift);
    bn_apply<<<(NGENE*CDIM+255)/256,256>>>(Hg, scale, shift, gene, NGENE*CDIM);
    // BN dis -> directly into output dis region (also GAT1 src features)
    zero_f<<<1,128>>>(s1, CDIM);
    zero_f<<<1,128>>>(s2, CDIM);
    col_stats<<<256,256>>>(Hd, NDIS, s1, s2);
    bn_finalize<<<1,128>>>(s1, s2, gd, betad, (float)NDIS, scale, shift);
    bn_apply<<<(NDIS*CDIM+255)/256,256>>>(Hd, scale, shift, out_dis, NDIS*CDIM);

    // ---- GAT relation 1: dis -> gene ----
    sgemm<0><<<dim3(4, (NDIS +127)/128), 256>>>(out_dis, W1s, nullptr, xs, NDIS,  512, 128);
    sgemm<0><<<dim3(4, (NGENE+127)/128), 256>>>(gene,    W1d, nullptr, xd, NGENE, 512, 128);
    att_scores<<<NDIS, 128>>>(xs, a1s, ls);
    att_scores<<<NGENE,128>>>(xd, a1d, ld);
    zero_i<<<(NGENE+255)/256,256>>>(cnt, NGENE);
    edge_count  <<<(E1N+NDIS+255)/256,256>>>(e1s, e1d, E1N, NDIS, cnt);
    exscan<<<1,1024>>>(cnt, rowptr, wptr, NGENE);
    edge_scatter<<<(E1N+NDIS+255)/256,256>>>(e1s, e1d, E1N, NDIS, wptr, elist);
    gat_aggregate<<<NGENE,128>>>(xs, ls, ld, rowptr, elist, gene, b1, gene);

    // ---- GAT relation 2: gene -> gene (updated gene) ----
    sgemm<0><<<dim3(4, (NGENE+127)/128), 256>>>(gene, W2s, nullptr, xs, NGENE, 512, 128);
    sgemm<0><<<dim3(4, (NGENE+127)/128), 256>>>(gene, W2d, nullptr, xd, NGENE, 512, 128);
    att_scores<<<NGENE,128>>>(xs, a2s, ls);
    att_scores<<<NGENE,128>>>(xd, a2d, ld);
    zero_i<<<(NGENE+255)/256,256>>>(cnt, NGENE);
    edge_count  <<<(E2N+NGENE+255)/256,256>>>(e2s, e2d, E2N, NGENE, cnt);
    exscan<<<1,1024>>>(cnt, rowptr, wptr, NGENE);
    edge_scatter<<<(E2N+NGENE+255)/256,256>>>(e2s, e2d, E2N, NGENE, wptr, elist);
    gat_aggregate<<<NGENE,128>>>(xs, ls, ld, rowptr, elist, gene, b2, out_gene);
}

// round 5
// speedup vs baseline: 1.3501x; 1.3501x over previous
#include <cuda_runtime.h>
#include <math.h>
#include <float.h>
#include <stdint.h>

#define NGENE 50000
#define NDIS  25000
#define E1N   150000
#define E2N   150000
#define CDIM  128
#define HC    512   /* H_HEADS * C_HID */

// ---------------- scratch (static __device__ — no allocation) ----------------
__device__ float g_Hg[NGENE*CDIM];
__device__ float g_Hd[NDIS*CDIM];
__device__ float g_gene[NGENE*CDIM];
__device__ float g_xs[NGENE*HC];
__device__ float g_xd[NGENE*HC];
__device__ float g_ls[NGENE*4];
__device__ float g_ld[NGENE*4];
__device__ float g_s1[CDIM];
__device__ float g_s2[CDIM];
__device__ float g_scale[CDIM];
__device__ float g_shift[CDIM];
__device__ int   g_cnt[NGENE];
__device__ int   g_rowptr[NGENE+1];
__device__ int   g_wptr[NGENE];
__device__ int   g_elist[E2N+NGENE];

// ---------------- utility kernels ----------------
__global__ void zero_f(float* p, int n){ int i = blockIdx.x*blockDim.x+threadIdx.x; if(i<n) p[i]=0.f; }
__global__ void zero_i(int* p, int n){ int i = blockIdx.x*blockDim.x+threadIdx.x; if(i<n) p[i]=0; }

// ---------------- 3xTF32 tensor-core GEMM (fp32-accurate) ----------------
// C[M,N] = A[M,K] @ B[K,N]  (+bias+relu if FUSED)
// CTA tile 128x128, BK=16, 256 threads = 8 warps of 64x32 (2x4 warp grid).
// Each operand split hi/lo via cvt.rna.tf32; D += al*bh + ah*bl + ah*bh.

__device__ __forceinline__ void cpa16(void* dst, const void* src, bool pred) {
    uint32_t d = (uint32_t)__cvta_generic_to_shared(dst);
    int sz = pred ? 16 : 0;
    asm volatile("cp.async.cg.shared.global [%0], [%1], 16, %2;\n"
                 :: "r"(d), "l"(src), "r"(sz));
}
__device__ __forceinline__ void cpa_commit() {
    asm volatile("cp.async.commit_group;\n" ::: "memory");
}
template<int NWAIT>
__device__ __forceinline__ void cpa_wait() {
    asm volatile("cp.async.wait_group %0;\n" :: "n"(NWAIT) : "memory");
}
__device__ __forceinline__ uint32_t f2tf(float f) {
    uint32_t u;
    asm("cvt.rna.tf32.f32 %0, %1;" : "=r"(u) : "f"(f));
    return u;
}
__device__ __forceinline__ void split_tf32(float v, uint32_t& hi, uint32_t& lo) {
    hi = f2tf(v);
    lo = f2tf(v - __uint_as_float(hi));
}
__device__ __forceinline__ void mma_tf32(float* c, const uint32_t* a, const uint32_t* b) {
    asm volatile(
        "mma.sync.aligned.m16n8k8.row.col.f32.tf32.tf32.f32 "
        "{%0,%1,%2,%3}, {%4,%5,%6,%7}, {%8,%9}, {%0,%1,%2,%3};\n"
        : "+f"(c[0]), "+f"(c[1]), "+f"(c[2]), "+f"(c[3])
        : "r"(a[0]), "r"(a[1]), "r"(a[2]), "r"(a[3]), "r"(b[0]), "r"(b[1]));
}

template<int FUSED>
__global__ __launch_bounds__(256)
void tgemm(const float* __restrict__ A, const float* __restrict__ B,
           const float* __restrict__ bias, float* __restrict__ C,
           int M, int N, int K)
{
    __shared__ float As[2][128][20];
    __shared__ float Bs[2][16][136];

    const int t = threadIdx.x;
    const int lane = t & 31, warp = t >> 5;
    const int g = lane >> 2, tg = lane & 3;
    const int warpM = warp >> 2, warpN = warp & 3;   // 2 x 4 warps
    const int m0 = blockIdx.y * 128, n0 = blockIdx.x * 128;

    float acc[4][4][4];
    #pragma unroll
    for (int mt=0; mt<4; mt++)
        #pragma unroll
        for (int nt=0; nt<4; nt++)
            #pragma unroll
            for (int i=0; i<4; i++) acc[mt][nt][i] = 0.f;

    const int ntiles = K >> 4;

    // A tile: 128 rows x 16 cols = 512 16B-chunks. chunk ch: m=ch>>2, kc=ch&3.
    const int a0m = t >> 2,        a0k = t & 3;          // ch = t
    const int a1m = (t+256) >> 2;                        // ch = t+256 (same kc)
    // B tile: 16 rows x 128 cols = 512 16B-chunks. chunk ch: k=ch>>5, nc=(ch&31)*4.
    const int b0k = t >> 5,        b0n = (t & 31) * 4;   // ch = t
    const int b1k = (t+256) >> 5;                        // ch = t+256 (same nc)

    // ---- prologue: stage 0 ----
    {
        bool p0 = (m0 + a0m) < M, p1 = (m0 + a1m) < M;
        cpa16(&As[0][a0m][a0k*4], A + (size_t)(m0+a0m)*K + a0k*4, p0);
        cpa16(&As[0][a1m][a0k*4], A + (size_t)(m0+a1m)*K + a0k*4, p1);
        cpa16(&Bs[0][b0k][b0n],   B + (size_t)b0k*N + n0 + b0n, true);
        cpa16(&Bs[0][b1k][b0n],   B + (size_t)b1k*N + n0 + b0n, true);
    }
    cpa_commit();

    for (int kt = 0; kt < ntiles; kt++) {
        const int cur = kt & 1;
        if (kt + 1 < ntiles) {
            const int nxt = (kt+1) & 1;
            const int k0 = (kt+1) << 4;
            bool p0 = (m0 + a0m) < M, p1 = (m0 + a1m) < M;
            cpa16(&As[nxt][a0m][a0k*4], A + (size_t)(m0+a0m)*K + k0 + a0k*4, p0);
            cpa16(&As[nxt][a1m][a0k*4], A + (size_t)(m0+a1m)*K + k0 + a0k*4, p1);
            cpa16(&Bs[nxt][b0k][b0n],   B + (size_t)(k0+b0k)*N + n0 + b0n, true);
            cpa16(&Bs[nxt][b1k][b0n],   B + (size_t)(k0+b1k)*N + n0 + b0n, true);
            cpa_commit();
            cpa_wait<1>();
        } else {
            cpa_commit();
            cpa_wait<0>();
        }
        __syncthreads();

        #pragma unroll
        for (int ks = 0; ks < 2; ks++) {
            const int kb = ks*8;
            uint32_t ah[4][4], al[4][4], bh[4][2], bl[4][2];
            #pragma unroll
            for (int mt = 0; mt < 4; mt++) {
                const int mr = warpM*64 + mt*16;
                split_tf32(As[cur][mr+g  ][kb+tg  ], ah[mt][0], al[mt][0]);
                split_tf32(As[cur][mr+g+8][kb+tg  ], ah[mt][1], al[mt][1]);
                split_tf32(As[cur][mr+g  ][kb+tg+4], ah[mt][2], al[mt][2]);
                split_tf32(As[cur][mr+g+8][kb+tg+4], ah[mt][3], al[mt][3]);
            }
            #pragma unroll
            for (int nt = 0; nt < 4; nt++) {
                const int nc = warpN*32 + nt*8 + g;
                split_tf32(Bs[cur][kb+tg  ][nc], bh[nt][0], bl[nt][0]);
                split_tf32(Bs[cur][kb+tg+4][nc], bh[nt][1], bl[nt][1]);
            }
            #pragma unroll
            for (int mt = 0; mt < 4; mt++)
                #pragma unroll
                for (int nt = 0; nt < 4; nt++) {
                    mma_tf32(acc[mt][nt], al[mt], bh[nt]);  // lo*hi first
                    mma_tf32(acc[mt][nt], ah[mt], bl[nt]);  // hi*lo
                    mma_tf32(acc[mt][nt], ah[mt], bh[nt]);  // hi*hi last
                }
        }
        __syncthreads();
    }

    // ---- epilogue ----
    #pragma unroll
    for (int mt = 0; mt < 4; mt++) {
        const int r0 = m0 + warpM*64 + mt*16 + g;
        #pragma unroll
        for (int nt = 0; nt < 4; nt++) {
            const int col = n0 + warpN*32 + nt*8 + tg*2;
            float2 v0 = make_float2(acc[mt][nt][0], acc[mt][nt][1]);
            float2 v1 = make_float2(acc[mt][nt][2], acc[mt][nt][3]);
            if (FUSED) {
                float b0 = bias[col], b1 = bias[col+1];
                v0.x = fmaxf(v0.x + b0, 0.f); v0.y = fmaxf(v0.y + b1, 0.f);
                v1.x = fmaxf(v1.x + b0, 0.f); v1.y = fmaxf(v1.y + b1, 0.f);
            }
            if (r0 < M)     *(float2*)&C[(size_t)r0*N + col]     = v0;
            if (r0 + 8 < M) *(float2*)&C[(size_t)(r0+8)*N + col] = v1;
        }
    }
}

// ---------------- BatchNorm stats (N=128 columns, row-major H) ----------------
__global__ __launch_bounds__(256)
void col_stats(const float* __restrict__ H, int M, float* s1, float* s2)
{
    int c = threadIdx.x & 127;
    int rhalf = threadIdx.x >> 7;
    float a = 0.f, b = 0.f;
    for (int r = blockIdx.x*2 + rhalf; r < M; r += gridDim.x*2) {
        float v = H[(size_t)r*128 + c];
        a += v; b += v*v;
    }
    __shared__ float sa[256], sb[256];
    sa[threadIdx.x]=a; sb[threadIdx.x]=b;
    __syncthreads();
    if (threadIdx.x < 128) {
        atomicAdd(&s1[c], sa[threadIdx.x]+sa[threadIdx.x+128]);
        atomicAdd(&s2[c], sb[threadIdx.x]+sb[threadIdx.x+128]);
    }
}

__global__ void bn_finalize(const float* s1, const float* s2,
                            const float* g, const float* beta,
                            float M, float* scale, float* shift)
{
    int c = threadIdx.x;  // 128
    float mu  = s1[c] / M;
    float var = s2[c] / M - mu*mu;
    float inv = rsqrtf(var + 1e-5f);
    scale[c] = g[c]*inv;
    shift[c] = beta[c] - mu*g[c]*inv;
}

__global__ void bn_apply(const float* __restrict__ H, const float* __restrict__ scale,
                         const float* __restrict__ shift, float* __restrict__ out, int n)
{
    int i = blockIdx.x*blockDim.x + threadIdx.x;
    if (i < n) { int c = i & 127; out[i] = H[i]*scale[c] + shift[c]; }
}

// ---------------- attention scores: l[n,h] = sum_c x[n,h,c]*a[h,c] ----------------
__global__ __launch_bounds__(128)
void att_scores(const float* __restrict__ x, const float* __restrict__ a,
                float* __restrict__ lout)
{
    int n = blockIdx.x; int c = threadIdx.x;
    const float* xr = x + (size_t)n*512;
    float v0 = xr[c]      * a[c];
    float v1 = xr[128+c]  * a[128+c];
    float v2 = xr[256+c]  * a[256+c];
    float v3 = xr[384+c]  * a[384+c];
    #pragma unroll
    for (int off=16; off; off>>=1) {
        v0 += __shfl_down_sync(0xffffffff, v0, off);
        v1 += __shfl_down_sync(0xffffffff, v1, off);
        v2 += __shfl_down_sync(0xffffffff, v2, off);
        v3 += __shfl_down_sync(0xffffffff, v3, off);
    }
    __shared__ float par[4][4];
    int warp = c >> 5, lane = c & 31;
    if (!lane) { par[0][warp]=v0; par[1][warp]=v1; par[2][warp]=v2; par[3][warp]=v3; }
    __syncthreads();
    if (c < 4) lout[(size_t)n*4 + c] = par[c][0]+par[c][1]+par[c][2]+par[c][3];
}

// ---------------- CSR build over destination nodes ----------------
__global__ void edge_count(const int* __restrict__ src, const int* __restrict__ dst,
                           int E, int nloop, int* cnt)
{
    int i = blockIdx.x*blockDim.x + threadIdx.x;
    if (i >= E + nloop) return;
    int d;
    if (i < E) { int s = src[i]; d = dst[i]; if (s == d) return; }
    else d = i - E;
    atomicAdd(&cnt[d], 1);
}

__global__ void edge_scatter(const int* __restrict__ src, const int* __restrict__ dst,
                             int E, int nloop, int* wptr, int* elist)
{
    int i = blockIdx.x*blockDim.x + threadIdx.x;
    if (i >= E + nloop) return;
    int s, d;
    if (i < E) { s = src[i]; d = dst[i]; if (s == d) return; }
    else { d = i - E; s = d; }
    int pos = atomicAdd(&wptr[d], 1);
    elist[pos] = s;
}

__global__ __launch_bounds__(1024)
void exscan(const int* __restrict__ cnt, int* __restrict__ rowptr,
            int* __restrict__ wptr, int n)
{
    __shared__ int sums[1024];
    int t = threadIdx.x;
    int chunk = (n + 1023) >> 10;
    int b = t*chunk, e = min(n, b+chunk);
    int s = 0;
    for (int i=b; i<e; i++) s += cnt[i];
    sums[t] = s;
    __syncthreads();
    for (int off=1; off<1024; off<<=1) {
        int v = (t >= off) ? sums[t-off] : 0;
        __syncthreads();
        sums[t] += v;
        __syncthreads();
    }
    int base = (t==0) ? 0 : sums[t-1];
    for (int i=b; i<e; i++) { rowptr[i]=base; wptr[i]=base; base += cnt[i]; }
    if (t == 1023) rowptr[n] = sums[1023];
}

// ---------------- per-dst softmax + gather aggregation ----------------
__global__ __launch_bounds__(128)
void gat_aggregate(const float* __restrict__ xs, const float* __restrict__ ls,
                   const float* __restrict__ ld,
                   const int* __restrict__ rowptr, const int* __restrict__ elist,
                   const float* __restrict__ base, const float* __restrict__ bias,
                   float* __restrict__ out)
{
    int d = blockIdx.x;
    int c = threadIdx.x;  // 128 threads = channel
    int e0 = rowptr[d], e1 = rowptr[d+1];

    __shared__ float sm[4], sdinv[4], sldv[4];
    __shared__ float w[128*4];
    __shared__ int   ssrc[128];

    if (c < 4) {
        float ldh = ld[(size_t)d*4 + c];
        sldv[c] = ldh;
        float mx = -3.0e38f;
        for (int e=e0; e<e1; e++) {
            int s = elist[e];
            float x = ls[(size_t)s*4 + c] + ldh;
            x = (x > 0.f) ? x : 0.2f*x;
            mx = fmaxf(mx, x);
        }
        float den = 0.f;
        for (int e=e0; e<e1; e++) {
            int s = elist[e];
            float x = ls[(size_t)s*4 + c] + ldh;
            x = (x > 0.f) ? x : 0.2f*x;
            den += __expf(x - mx);
        }
        sm[c] = mx;
        sdinv[c] = (e1 > e0) ? (1.f/den) : 0.f;
    }
    __syncthreads();

    float a0=0.f, a1=0.f, a2=0.f, a3=0.f;
    for (int eb=e0; eb<e1; eb+=128) {
        int ne = min(128, e1-eb);
        if (c < ne) ssrc[c] = elist[eb + c];
        __syncthreads();
        for (int t=c; t < ne*4; t += 128) {
            int e = t >> 2, h = t & 3;
            int s = ssrc[e];
            float x = ls[(size_t)s*4 + h] + sldv[h];
            x = (x > 0.f) ? x : 0.2f*x;
            w[t] = __expf(x - sm[h]) * sdinv[h];
        }
        __syncthreads();
        for (int e=0; e<ne; e++) {
            const float* xr = xs + (size_t)ssrc[e]*512;
            float4 ww = *(const float4*)&w[e*4];
            a0 += ww.x * xr[c];
            a1 += ww.y * xr[128+c];
            a2 += ww.z * xr[256+c];
            a3 += ww.w * xr[384+c];
        }
        __syncthreads();
    }
    size_t oi = (size_t)d*128 + c;
    out[oi] = base[oi] + 0.25f*(a0+a1+a2+a3) + bias[c];
}

// ---------------- launch ----------------
extern "C" void kernel_launch(void* const* d_in, const int* in_sizes, int n_in,
                              void* d_out, int out_size)
{
    const float* x_gene = (const float*)d_in[0];
    const float* x_dis  = (const float*)d_in[1];
    const int*   e1s    = (const int*)d_in[2];
    const int*   e1d    = (const int*)d_in[3];
    const int*   e2s    = (const int*)d_in[4];
    const int*   e2d    = (const int*)d_in[5];
    const float* Wg    = (const float*)d_in[6];
    const float* bg    = (const float*)d_in[7];
    const float* gg    = (const float*)d_in[8];
    const float* betag = (const float*)d_in[9];
    const float* Wd    = (const float*)d_in[10];
    const float* bd    = (const float*)d_in[11];
    const float* gd    = (const float*)d_in[12];
    const float* betad = (const float*)d_in[13];
    const float* W1s = (const float*)d_in[14];
    const float* W1d = (const float*)d_in[15];
    const float* a1s = (const float*)d_in[16];
    const float* a1d = (const float*)d_in[17];
    const float* b1  = (const float*)d_in[18];
    const float* W2s = (const float*)d_in[19];
    const float* W2d = (const float*)d_in[20];
    const float* a2s = (const float*)d_in[21];
    const float* a2d = (const float*)d_in[22];
    const float* b2  = (const float*)d_in[23];

    float *Hg,*Hd,*gene,*xs,*xd,*ls,*ld,*s1,*s2,*scale,*shift;
    int *cnt,*rowptr,*wptr,*elist;
    cudaGetSymbolAddress((void**)&Hg,    g_Hg);
    cudaGetSymbolAddress((void**)&Hd,    g_Hd);
    cudaGetSymbolAddress((void**)&gene,  g_gene);
    cudaGetSymbolAddress((void**)&xs,    g_xs);
    cudaGetSymbolAddress((void**)&xd,    g_xd);
    cudaGetSymbolAddress((void**)&ls,    g_ls);
    cudaGetSymbolAddress((void**)&ld,    g_ld);
    cudaGetSymbolAddress((void**)&s1,    g_s1);
    cudaGetSymbolAddress((void**)&s2,    g_s2);
    cudaGetSymbolAddress((void**)&scale, g_scale);
    cudaGetSymbolAddress((void**)&shift, g_shift);
    cudaGetSymbolAddress((void**)&cnt,   g_cnt);
    cudaGetSymbolAddress((void**)&rowptr,g_rowptr);
    cudaGetSymbolAddress((void**)&wptr,  g_wptr);
    cudaGetSymbolAddress((void**)&elist, g_elist);

    float* out_gene = (float*)d_out;
    float* out_dis  = (float*)d_out + (size_t)NGENE*CDIM;

    // ---- encoders: h = relu(x@W + b) ----
    tgemm<1><<<dim3(1, (NGENE+127)/128), 256>>>(x_gene, Wg, bg, Hg, NGENE, 128, 512);
    tgemm<1><<<dim3(1, (NDIS +127)/128), 256>>>(x_dis,  Wd, bd, Hd, NDIS,  128, 256);

    // BN gene
    zero_f<<<1,128>>>(s1, CDIM);
    zero_f<<<1,128>>>(s2, CDIM);
    col_stats<<<256,256>>>(Hg, NGENE, s1, s2);
    bn_finalize<<<1,128>>>(s1, s2, gg, betag, (float)NGENE, scale, shift);
    bn_apply<<<(NGENE*CDIM+255)/256,256>>>(Hg, scale, shift, gene, NGENE*CDIM);
    // BN dis -> directly into output dis region (also GAT1 src features)
    zero_f<<<1,128>>>(s1, CDIM);
    zero_f<<<1,128>>>(s2, CDIM);
    col_stats<<<256,256>>>(Hd, NDIS, s1, s2);
    bn_finalize<<<1,128>>>(s1, s2, gd, betad, (float)NDIS, scale, shift);
    bn_apply<<<(NDIS*CDIM+255)/256,256>>>(Hd, scale, shift, out_dis, NDIS*CDIM);

    // ---- GAT relation 1: dis -> gene ----
    tgemm<0><<<dim3(4, (NDIS +127)/128), 256>>>(out_dis, W1s, nullptr, xs, NDIS,  512, 128);
    tgemm<0><<<dim3(4, (NGENE+127)/128), 256>>>(gene,    W1d, nullptr, xd, NGENE, 512, 128);
    att_scores<<<NDIS, 128>>>(xs, a1s, ls);
    att_scores<<<NGENE,128>>>(xd, a1d, ld);
    zero_i<<<(NGENE+255)/256,256>>>(cnt, NGENE);
    edge_count  <<<(E1N+NDIS+255)/256,256>>>(e1s, e1d, E1N, NDIS, cnt);
    exscan<<<1,1024>>>(cnt, rowptr, wptr, NGENE);
    edge_scatter<<<(E1N+NDIS+255)/256,256>>>(e1s, e1d, E1N, NDIS, wptr, elist);
    gat_aggregate<<<NGENE,128>>>(xs, ls, ld, rowptr, elist, gene, b1, gene);

    // ---- GAT relation 2: gene -> gene (updated gene) ----
    tgemm<0><<<dim3(4, (NGENE+127)/128), 256>>>(gene, W2s, nullptr, xs, NGENE, 512, 128);
    tgemm<0><<<dim3(4, (NGENE+127)/128), 256>>>(gene, W2d, nullptr, xd, NGENE, 512, 128);
    att_scores<<<NGENE,128>>>(xs, a2s, ls);
    att_scores<<<NGENE,128>>>(xd, a2d, ld);
    zero_i<<<(NGENE+255)/256,256>>>(cnt, NGENE);
    edge_count  <<<(E2N+NGENE+255)/256,256>>>(e2s, e2d, E2N, NGENE, cnt);
    exscan<<<1,1024>>>(cnt, rowptr, wptr, NGENE);
    edge_scatter<<<(E2N+NGENE+255)/256,256>>>(e2s, e2d, E2N, NGENE, wptr, elist);
    gat_aggregate<<<NGENE,128>>>(xs, ls, ld, rowptr, elist, gene, b2, out_gene);
}

// round 6
// speedup vs baseline: 1.7882x; 1.3245x over previous
#include <cuda_runtime.h>
#include <math.h>
#include <float.h>
#include <stdint.h>

#define NGENE 50000
#define NDIS  25000
#define E1N   150000
#define E2N   150000
#define CDIM  128
#define HC    512   /* H_HEADS * C_HID */

// ---------------- scratch (static __device__ — no allocation) ----------------
__device__ float g_Hg[NGENE*CDIM];
__device__ float g_Hd[NDIS*CDIM];
__device__ float g_gene[NGENE*CDIM];
__device__ float g_xs[NGENE*HC];
__device__ float g_xd[NGENE*HC];
__device__ float g_ls[NGENE*4];
__device__ float g_ld[NGENE*4];
__device__ float g_s1[CDIM];
__device__ float g_s2[CDIM];
__device__ float g_scale[CDIM];
__device__ float g_shift[CDIM];
__device__ int   g_cnt[NGENE];
__device__ int   g_rowptr[NGENE+1];
__device__ int   g_wptr[NGENE];
__device__ int   g_elist[E2N+NGENE];

// ---------------- utility kernels ----------------
__global__ void zero_f(float* p, int n){ int i = blockIdx.x*blockDim.x+threadIdx.x; if(i<n) p[i]=0.f; }
__global__ void zero_i(int* p, int n){ int i = blockIdx.x*blockDim.x+threadIdx.x; if(i<n) p[i]=0; }

// ---------------- bf16 3-product tensor-core GEMM (near-fp32 accurate) ----------------
// C[M,N] = A[M,K] @ B[K,N]  (+bias+relu if FUSED)
// CTA tile 128x128, BK=16, 256 threads = 8 warps of 64x32 (2x4 warp grid).
// x = hi + lo (bf16 each); D += al*bh + ah*bl + ah*bh  (al*bl dropped, ~2^-16 rel).
// mma.sync.m16n8k16.bf16 with fp32 accumulate.

__device__ __forceinline__ void cpa16(void* dst, const void* src, bool pred) {
    uint32_t d = (uint32_t)__cvta_generic_to_shared(dst);
    int sz = pred ? 16 : 0;
    asm volatile("cp.async.cg.shared.global [%0], [%1], 16, %2;\n"
                 :: "r"(d), "l"(src), "r"(sz));
}
__device__ __forceinline__ void cpa_commit() {
    asm volatile("cp.async.commit_group;\n" ::: "memory");
}
template<int NWAIT>
__device__ __forceinline__ void cpa_wait() {
    asm volatile("cp.async.wait_group %0;\n" :: "n"(NWAIT) : "memory");
}

// pack two fp32 into bf16x2 {lo=x0, hi=x1}, and the residual pair
__device__ __forceinline__ void split2(float x0, float x1, uint32_t& hi, uint32_t& lo) {
    uint32_t h;
    asm("cvt.rn.bf16x2.f32 %0, %1, %2;" : "=r"(h) : "f"(x1), "f"(x0));
    float r0 = x0 - __uint_as_float(h << 16);
    float r1 = x1 - __uint_as_float(h & 0xffff0000u);
    uint32_t l;
    asm("cvt.rn.bf16x2.f32 %0, %1, %2;" : "=r"(l) : "f"(r1), "f"(r0));
    hi = h; lo = l;
}
__device__ __forceinline__ void mma_bf16(float* c, const uint32_t* a, const uint32_t* b) {
    asm volatile(
        "mma.sync.aligned.m16n8k16.row.col.f32.bf16.bf16.f32 "
        "{%0,%1,%2,%3}, {%4,%5,%6,%7}, {%8,%9}, {%0,%1,%2,%3};\n"
        : "+f"(c[0]), "+f"(c[1]), "+f"(c[2]), "+f"(c[3])
        : "r"(a[0]), "r"(a[1]), "r"(a[2]), "r"(a[3]), "r"(b[0]), "r"(b[1]));
}

template<int FUSED>
__global__ __launch_bounds__(256)
void tgemm(const float* __restrict__ A, const float* __restrict__ B,
           const float* __restrict__ bias, float* __restrict__ C,
           int M, int N, int K)
{
    __shared__ float As[2][128][20];
    __shared__ float Bs[2][16][132];

    const int t = threadIdx.x;
    const int lane = t & 31, warp = t >> 5;
    const int g = lane >> 2, tg = lane & 3;
    const int warpM = warp >> 2, warpN = warp & 3;   // 2 x 4 warps
    const int m0 = blockIdx.y * 128, n0 = blockIdx.x * 128;

    float acc[4][4][4];
    #pragma unroll
    for (int mt=0; mt<4; mt++)
        #pragma unroll
        for (int nt=0; nt<4; nt++)
            #pragma unroll
            for (int i=0; i<4; i++) acc[mt][nt][i] = 0.f;

    const int ntiles = K >> 4;

    // A tile: 128 rows x 16 cols = 512 16B-chunks. chunk ch: m=ch>>2, kc=ch&3.
    const int a0m = t >> 2,        a0k = t & 3;          // ch = t
    const int a1m = (t+256) >> 2;                        // ch = t+256 (same kc)
    // B tile: 16 rows x 128 cols = 512 16B-chunks. chunk ch: k=ch>>5, nc=(ch&31)*4.
    const int b0k = t >> 5,        b0n = (t & 31) * 4;   // ch = t
    const int b1k = (t+256) >> 5;                        // ch = t+256 (same nc)

    // ---- prologue: stage 0 ----
    {
        bool p0 = (m0 + a0m) < M, p1 = (m0 + a1m) < M;
        cpa16(&As[0][a0m][a0k*4], A + (size_t)(m0+a0m)*K + a0k*4, p0);
        cpa16(&As[0][a1m][a0k*4], A + (size_t)(m0+a1m)*K + a0k*4, p1);
        cpa16(&Bs[0][b0k][b0n],   B + (size_t)b0k*N + n0 + b0n, true);
        cpa16(&Bs[0][b1k][b0n],   B + (size_t)b1k*N + n0 + b0n, true);
    }
    cpa_commit();

    for (int kt = 0; kt < ntiles; kt++) {
        const int cur = kt & 1;
        if (kt + 1 < ntiles) {
            const int nxt = (kt+1) & 1;
            const int k0 = (kt+1) << 4;
            bool p0 = (m0 + a0m) < M, p1 = (m0 + a1m) < M;
            cpa16(&As[nxt][a0m][a0k*4], A + (size_t)(m0+a0m)*K + k0 + a0k*4, p0);
            cpa16(&As[nxt][a1m][a0k*4], A + (size_t)(m0+a1m)*K + k0 + a0k*4, p1);
            cpa16(&Bs[nxt][b0k][b0n],   B + (size_t)(k0+b0k)*N + n0 + b0n, true);
            cpa16(&Bs[nxt][b1k][b0n],   B + (size_t)(k0+b1k)*N + n0 + b0n, true);
            cpa_commit();
            cpa_wait<1>();
        } else {
            cpa_commit();
            cpa_wait<0>();
        }
        __syncthreads();

        // fragments for the whole BK=16 slice (one k16 MMA step)
        uint32_t ah[4][4], al[4][4], bh[4][2], bl[4][2];
        #pragma unroll
        for (int mt = 0; mt < 4; mt++) {
            const int mr = warpM*64 + mt*16;
            float2 p0 = *(const float2*)&As[cur][mr+g  ][2*tg  ];
            float2 p1 = *(const float2*)&As[cur][mr+g+8][2*tg  ];
            float2 p2 = *(const float2*)&As[cur][mr+g  ][2*tg+8];
            float2 p3 = *(const float2*)&As[cur][mr+g+8][2*tg+8];
            split2(p0.x, p0.y, ah[mt][0], al[mt][0]);
            split2(p1.x, p1.y, ah[mt][1], al[mt][1]);
            split2(p2.x, p2.y, ah[mt][2], al[mt][2]);
            split2(p3.x, p3.y, ah[mt][3], al[mt][3]);
        }
        #pragma unroll
        for (int nt = 0; nt < 4; nt++) {
            const int nc = warpN*32 + nt*8 + g;
            float q0 = Bs[cur][2*tg  ][nc];
            float q1 = Bs[cur][2*tg+1][nc];
            float q2 = Bs[cur][2*tg+8][nc];
            float q3 = Bs[cur][2*tg+9][nc];
            split2(q0, q1, bh[nt][0], bl[nt][0]);
            split2(q2, q3, bh[nt][1], bl[nt][1]);
        }
        #pragma unroll
        for (int mt = 0; mt < 4; mt++)
            #pragma unroll
            for (int nt = 0; nt < 4; nt++) {
                mma_bf16(acc[mt][nt], al[mt], bh[nt]);  // lo*hi
                mma_bf16(acc[mt][nt], ah[mt], bl[nt]);  // hi*lo
                mma_bf16(acc[mt][nt], ah[mt], bh[nt]);  // hi*hi last
            }
        __syncthreads();
    }

    // ---- epilogue ----
    #pragma unroll
    for (int mt = 0; mt < 4; mt++) {
        const int r0 = m0 + warpM*64 + mt*16 + g;
        #pragma unroll
        for (int nt = 0; nt < 4; nt++) {
            const int col = n0 + warpN*32 + nt*8 + tg*2;
            float2 v0 = make_float2(acc[mt][nt][0], acc[mt][nt][1]);
            float2 v1 = make_float2(acc[mt][nt][2], acc[mt][nt][3]);
            if (FUSED) {
                float b0 = bias[col], b1 = bias[col+1];
                v0.x = fmaxf(v0.x + b0, 0.f); v0.y = fmaxf(v0.y + b1, 0.f);
                v1.x = fmaxf(v1.x + b0, 0.f); v1.y = fmaxf(v1.y + b1, 0.f);
            }
            if (r0 < M)     *(float2*)&C[(size_t)r0*N + col]     = v0;
            if (r0 + 8 < M) *(float2*)&C[(size_t)(r0+8)*N + col] = v1;
        }
    }
}

// ---------------- BatchNorm stats (N=128 columns, row-major H) ----------------
__global__ __launch_bounds__(256)
void col_stats(const float* __restrict__ H, int M, float* s1, float* s2)
{
    int c = threadIdx.x & 127;
    int rhalf = threadIdx.x >> 7;
    float a = 0.f, b = 0.f;
    for (int r = blockIdx.x*2 + rhalf; r < M; r += gridDim.x*2) {
        float v = H[(size_t)r*128 + c];
        a += v; b += v*v;
    }
    __shared__ float sa[256], sb[256];
    sa[threadIdx.x]=a; sb[threadIdx.x]=b;
    __syncthreads();
    if (threadIdx.x < 128) {
        atomicAdd(&s1[c], sa[threadIdx.x]+sa[threadIdx.x+128]);
        atomicAdd(&s2[c], sb[threadIdx.x]+sb[threadIdx.x+128]);
    }
}

__global__ void bn_finalize(const float* s1, const float* s2,
                            const float* g, const float* beta,
                            float M, float* scale, float* shift)
{
    int c = threadIdx.x;  // 128
    float mu  = s1[c] / M;
    float var = s2[c] / M - mu*mu;
    float inv = rsqrtf(var + 1e-5f);
    scale[c] = g[c]*inv;
    shift[c] = beta[c] - mu*g[c]*inv;
}

__global__ void bn_apply(const float* __restrict__ H, const float* __restrict__ scale,
                         const float* __restrict__ shift, float* __restrict__ out, int n)
{
    int i = blockIdx.x*blockDim.x + threadIdx.x;
    if (i < n) { int c = i & 127; out[i] = H[i]*scale[c] + shift[c]; }
}

// ---------------- attention scores: l[n,h] = sum_c x[n,h,c]*a[h,c] ----------------
__global__ __launch_bounds__(128)
void att_scores(const float* __restrict__ x, const float* __restrict__ a,
                float* __restrict__ lout)
{
    int n = blockIdx.x; int c = threadIdx.x;
    const float* xr = x + (size_t)n*512;
    float v0 = xr[c]      * a[c];
    float v1 = xr[128+c]  * a[128+c];
    float v2 = xr[256+c]  * a[256+c];
    float v3 = xr[384+c]  * a[384+c];
    #pragma unroll
    for (int off=16; off; off>>=1) {
        v0 += __shfl_down_sync(0xffffffff, v0, off);
        v1 += __shfl_down_sync(0xffffffff, v1, off);
        v2 += __shfl_down_sync(0xffffffff, v2, off);
        v3 += __shfl_down_sync(0xffffffff, v3, off);
    }
    __shared__ float par[4][4];
    int warp = c >> 5, lane = c & 31;
    if (!lane) { par[0][warp]=v0; par[1][warp]=v1; par[2][warp]=v2; par[3][warp]=v3; }
    __syncthreads();
    if (c < 4) lout[(size_t)n*4 + c] = par[c][0]+par[c][1]+par[c][2]+par[c][3];
}

// ---------------- CSR build over destination nodes ----------------
__global__ void edge_count(const int* __restrict__ src, const int* __restrict__ dst,
                           int E, int nloop, int* cnt)
{
    int i = blockIdx.x*blockDim.x + threadIdx.x;
    if (i >= E + nloop) return;
    int d;
    if (i < E) { int s = src[i]; d = dst[i]; if (s == d) return; }
    else d = i - E;
    atomicAdd(&cnt[d], 1);
}

__global__ void edge_scatter(const int* __restrict__ src, const int* __restrict__ dst,
                             int E, int nloop, int* wptr, int* elist)
{
    int i = blockIdx.x*blockDim.x + threadIdx.x;
    if (i >= E + nloop) return;
    int s, d;
    if (i < E) { s = src[i]; d = dst[i]; if (s == d) return; }
    else { d = i - E; s = d; }
    int pos = atomicAdd(&wptr[d], 1);
    elist[pos] = s;
}

__global__ __launch_bounds__(1024)
void exscan(const int* __restrict__ cnt, int* __restrict__ rowptr,
            int* __restrict__ wptr, int n)
{
    __shared__ int sums[1024];
    int t = threadIdx.x;
    int chunk = (n + 1023) >> 10;
    int b = t*chunk, e = min(n, b+chunk);
    int s = 0;
    for (int i=b; i<e; i++) s += cnt[i];
    sums[t] = s;
    __syncthreads();
    for (int off=1; off<1024; off<<=1) {
        int v = (t >= off) ? sums[t-off] : 0;
        __syncthreads();
        sums[t] += v;
        __syncthreads();
    }
    int base = (t==0) ? 0 : sums[t-1];
    for (int i=b; i<e; i++) { rowptr[i]=base; wptr[i]=base; base += cnt[i]; }
    if (t == 1023) rowptr[n] = sums[1023];
}

// ---------------- per-dst softmax + gather aggregation ----------------
__global__ __launch_bounds__(128)
void gat_aggregate(const float* __restrict__ xs, const float* __restrict__ ls,
                   const float* __restrict__ ld,
                   const int* __restrict__ rowptr, const int* __restrict__ elist,
                   const float* __restrict__ base, const float* __restrict__ bias,
                   float* __restrict__ out)
{
    int d = blockIdx.x;
    int c = threadIdx.x;  // 128 threads = channel
    int e0 = rowptr[d], e1 = rowptr[d+1];

    __shared__ float sm[4], sdinv[4], sldv[4];
    __shared__ float w[128*4];
    __shared__ int   ssrc[128];

    if (c < 4) {
        float ldh = ld[(size_t)d*4 + c];
        sldv[c] = ldh;
        float mx = -3.0e38f;
        for (int e=e0; e<e1; e++) {
            int s = elist[e];
            float x = ls[(size_t)s*4 + c] + ldh;
            x = (x > 0.f) ? x : 0.2f*x;
            mx = fmaxf(mx, x);
        }
        float den = 0.f;
        for (int e=e0; e<e1; e++) {
            int s = elist[e];
            float x = ls[(size_t)s*4 + c] + ldh;
            x = (x > 0.f) ? x : 0.2f*x;
            den += __expf(x - mx);
        }
        sm[c] = mx;
        sdinv[c] = (e1 > e0) ? (1.f/den) : 0.f;
    }
    __syncthreads();

    float a0=0.f, a1=0.f, a2=0.f, a3=0.f;
    for (int eb=e0; eb<e1; eb+=128) {
        int ne = min(128, e1-eb);
        if (c < ne) ssrc[c] = elist[eb + c];
        __syncthreads();
        for (int t=c; t < ne*4; t += 128) {
            int e = t >> 2, h = t & 3;
            int s = ssrc[e];
            float x = ls[(size_t)s*4 + h] + sldv[h];
            x = (x > 0.f) ? x : 0.2f*x;
            w[t] = __expf(x - sm[h]) * sdinv[h];
        }
        __syncthreads();
        for (int e=0; e<ne; e++) {
            const float* xr = xs + (size_t)ssrc[e]*512;
            float4 ww = *(const float4*)&w[e*4];
            a0 += ww.x * xr[c];
            a1 += ww.y * xr[128+c];
            a2 += ww.z * xr[256+c];
            a3 += ww.w * xr[384+c];
        }
        __syncthreads();
    }
    size_t oi = (size_t)d*128 + c;
    out[oi] = base[oi] + 0.25f*(a0+a1+a2+a3) + bias[c];
}

// ---------------- launch ----------------
extern "C" void kernel_launch(void* const* d_in, const int* in_sizes, int n_in,
                              void* d_out, int out_size)
{
    const float* x_gene = (const float*)d_in[0];
    const float* x_dis  = (const float*)d_in[1];
    const int*   e1s    = (const int*)d_in[2];
    const int*   e1d    = (const int*)d_in[3];
    const int*   e2s    = (const int*)d_in[4];
    const int*   e2d    = (const int*)d_in[5];
    const float* Wg    = (const float*)d_in[6];
    const float* bg    = (const float*)d_in[7];
    const float* gg    = (const float*)d_in[8];
    const float* betag = (const float*)d_in[9];
    const float* Wd    = (const float*)d_in[10];
    const float* bd    = (const float*)d_in[11];
    const float* gd    = (const float*)d_in[12];
    const float* betad = (const float*)d_in[13];
    const float* W1s = (const float*)d_in[14];
    const float* W1d = (const float*)d_in[15];
    const float* a1s = (const float*)d_in[16];
    const float* a1d = (const float*)d_in[17];
    const float* b1  = (const float*)d_in[18];
    const float* W2s = (const float*)d_in[19];
    const float* W2d = (const float*)d_in[20];
    const float* a2s = (const float*)d_in[21];
    const float* a2d = (const float*)d_in[22];
    const float* b2  = (const float*)d_in[23];

    float *Hg,*Hd,*gene,*xs,*xd,*ls,*ld,*s1,*s2,*scale,*shift;
    int *cnt,*rowptr,*wptr,*elist;
    cudaGetSymbolAddress((void**)&Hg,    g_Hg);
    cudaGetSymbolAddress((void**)&Hd,    g_Hd);
    cudaGetSymbolAddress((void**)&gene,  g_gene);
    cudaGetSymbolAddress((void**)&xs,    g_xs);
    cudaGetSymbolAddress((void**)&xd,    g_xd);
    cudaGetSymbolAddress((void**)&ls,    g_ls);
    cudaGetSymbolAddress((void**)&ld,    g_ld);
    cudaGetSymbolAddress((void**)&s1,    g_s1);
    cudaGetSymbolAddress((void**)&s2,    g_s2);
    cudaGetSymbolAddress((void**)&scale, g_scale);
    cudaGetSymbolAddress((void**)&shift, g_shift);
    cudaGetSymbolAddress((void**)&cnt,   g_cnt);
    cudaGetSymbolAddress((void**)&rowptr,g_rowptr);
    cudaGetSymbolAddress((void**)&wptr,  g_wptr);
    cudaGetSymbolAddress((void**)&elist, g_elist);

    float* out_gene = (float*)d_out;
    float* out_dis  = (float*)d_out + (size_t)NGENE*CDIM;

    // ---- encoders: h = relu(x@W + b) ----
    tgemm<1><<<dim3(1, (NGENE+127)/128), 256>>>(x_gene, Wg, bg, Hg, NGENE, 128, 512);
    tgemm<1><<<dim3(1, (NDIS +127)/128), 256>>>(x_dis,  Wd, bd, Hd, NDIS,  128, 256);

    // BN gene
    zero_f<<<1,128>>>(s1, CDIM);
    zero_f<<<1,128>>>(s2, CDIM);
    col_stats<<<256,256>>>(Hg, NGENE, s1, s2);
    bn_finalize<<<1,128>>>(s1, s2, gg, betag, (float)NGENE, scale, shift);
    bn_apply<<<(NGENE*CDIM+255)/256,256>>>(Hg, scale, shift, gene, NGENE*CDIM);
    // BN dis -> directly into output dis region (also GAT1 src features)
    zero_f<<<1,128>>>(s1, CDIM);
    zero_f<<<1,128>>>(s2, CDIM);
    col_stats<<<256,256>>>(Hd, NDIS, s1, s2);
    bn_finalize<<<1,128>>>(s1, s2, gd, betad, (float)NDIS, scale, shift);
    bn_apply<<<(NDIS*CDIM+255)/256,256>>>(Hd, scale, shift, out_dis, NDIS*CDIM);

    // ---- GAT relation 1: dis -> gene ----
    tgemm<0><<<dim3(4, (NDIS +127)/128), 256>>>(out_dis, W1s, nullptr, xs, NDIS,  512, 128);
    tgemm<0><<<dim3(4, (NGENE+127)/128), 256>>>(gene,    W1d, nullptr, xd, NGENE, 512, 128);
    att_scores<<<NDIS, 128>>>(xs, a1s, ls);
    att_scores<<<NGENE,128>>>(xd, a1d, ld);
    zero_i<<<(NGENE+255)/256,256>>>(cnt, NGENE);
    edge_count  <<<(E1N+NDIS+255)/256,256>>>(e1s, e1d, E1N, NDIS, cnt);
    exscan<<<1,1024>>>(cnt, rowptr, wptr, NGENE);
    edge_scatter<<<(E1N+NDIS+255)/256,256>>>(e1s, e1d, E1N, NDIS, wptr, elist);
    gat_aggregate<<<NGENE,128>>>(xs, ls, ld, rowptr, elist, gene, b1, gene);

    // ---- GAT relation 2: gene -> gene (updated gene) ----
    tgemm<0><<<dim3(4, (NGENE+127)/128), 256>>>(gene, W2s, nullptr, xs, NGENE, 512, 128);
    tgemm<0><<<dim3(4, (NGENE+127)/128), 256>>>(gene, W2d, nullptr, xd, NGENE, 512, 128);
    att_scores<<<NGENE,128>>>(xs, a2s, ls);
    att_scores<<<NGENE,128>>>(xd, a2d, ld);
    zero_i<<<(NGENE+255)/256,256>>>(cnt, NGENE);
    edge_count  <<<(E2N+NGENE+255)/256,256>>>(e2s, e2d, E2N, NGENE, cnt);
    exscan<<<1,1024>>>(cnt, rowptr, wptr, NGENE);
    edge_scatter<<<(E2N+NGENE+255)/256,256>>>(e2s, e2d, E2N, NGENE, wptr, elist);
    gat_aggregate<<<NGENE,128>>>(xs, ls, ld, rowptr, elist, gene, b2, out_gene);
}

// round 8
// speedup vs baseline: 1.8651x; 1.0429x over previous
#include <cuda_runtime.h>
#include <math.h>
#include <float.h>
#include <stdint.h>

#define NGENE 50000
#define NDIS  25000
#define E1N   150000
#define E2N   150000
#define CDIM  128
#define HC    512   /* H_HEADS * C_HID */

// ---------------- scratch (static __device__ — no allocation) ----------------
__device__ float g_Hg[NGENE*CDIM];
__device__ float g_Hd[NDIS*CDIM];
__device__ float g_gene[NGENE*CDIM];
__device__ float g_xs[NGENE*HC];
__device__ float g_ls[NGENE*4];
__device__ float g_ld[NGENE*4];
__device__ float g_s1[CDIM];
__device__ float g_s2[CDIM];
__device__ float g_scale[CDIM];
__device__ float g_shift[CDIM];
__device__ float g_wt_s[CDIM*4];
__device__ float g_wt_d[CDIM*4];
__device__ int   g_cnt[NGENE];
__device__ int   g_rowptr[NGENE+1];
__device__ int   g_wptr[NGENE];
__device__ int   g_elist[E2N+NGENE];

// ---------------- utility kernels ----------------
__global__ void zero_f(float* p, int n){ int i = blockIdx.x*blockDim.x+threadIdx.x; if(i<n) p[i]=0.f; }
__global__ void zero_i(int* p, int n){ int i = blockIdx.x*blockDim.x+threadIdx.x; if(i<n) p[i]=0; }

// ---------------- bf16 3-product tensor-core GEMM (near-fp32 accurate) ----------------
__device__ __forceinline__ void cpa16(void* dst, const void* src, bool pred) {
    uint32_t d = (uint32_t)__cvta_generic_to_shared(dst);
    int sz = pred ? 16 : 0;
    asm volatile("cp.async.cg.shared.global [%0], [%1], 16, %2;\n"
                 :: "r"(d), "l"(src), "r"(sz));
}
__device__ __forceinline__ void cpa_commit() {
    asm volatile("cp.async.commit_group;\n" ::: "memory");
}
template<int NWAIT>
__device__ __forceinline__ void cpa_wait() {
    asm volatile("cp.async.wait_group %0;\n" :: "n"(NWAIT) : "memory");
}

// pack two fp32 into bf16x2 {lo=x0, hi=x1}, and the residual pair
__device__ __forceinline__ void split2(float x0, float x1, uint32_t& hi, uint32_t& lo) {
    uint32_t h;
    asm("cvt.rn.bf16x2.f32 %0, %1, %2;" : "=r"(h) : "f"(x1), "f"(x0));
    float r0 = x0 - __uint_as_float(h << 16);
    float r1 = x1 - __uint_as_float(h & 0xffff0000u);
    uint32_t l;
    asm("cvt.rn.bf16x2.f32 %0, %1, %2;" : "=r"(l) : "f"(r1), "f"(r0));
    hi = h; lo = l;
}
__device__ __forceinline__ void mma_bf16(float* c, const uint32_t* a, const uint32_t* b) {
    asm volatile(
        "mma.sync.aligned.m16n8k16.row.col.f32.bf16.bf16.f32 "
        "{%0,%1,%2,%3}, {%4,%5,%6,%7}, {%8,%9}, {%0,%1,%2,%3};\n"
        : "+f"(c[0]), "+f"(c[1]), "+f"(c[2]), "+f"(c[3])
        : "r"(a[0]), "r"(a[1]), "r"(a[2]), "r"(a[3]), "r"(b[0]), "r"(b[1]));
}

template<int FUSED>
__global__ __launch_bounds__(256)
void tgemm(const float* __restrict__ A, const float* __restrict__ B,
           const float* __restrict__ bias, float* __restrict__ C,
           int M, int N, int K)
{
    __shared__ float As[2][128][20];
    __shared__ float Bs[2][16][132];

    const int t = threadIdx.x;
    const int lane = t & 31, warp = t >> 5;
    const int g = lane >> 2, tg = lane & 3;
    const int warpM = warp >> 2, warpN = warp & 3;   // 2 x 4 warps
    const int m0 = blockIdx.y * 128, n0 = blockIdx.x * 128;

    float acc[4][4][4];
    #pragma unroll
    for (int mt=0; mt<4; mt++)
        #pragma unroll
        for (int nt=0; nt<4; nt++)
            #pragma unroll
            for (int i=0; i<4; i++) acc[mt][nt][i] = 0.f;

    const int ntiles = K >> 4;

    const int a0m = t >> 2,        a0k = t & 3;          // ch = t
    const int a1m = (t+256) >> 2;                        // ch = t+256 (same kc)
    const int b0k = t >> 5,        b0n = (t & 31) * 4;   // ch = t
    const int b1k = (t+256) >> 5;                        // ch = t+256 (same nc)

    {
        bool p0 = (m0 + a0m) < M, p1 = (m0 + a1m) < M;
        cpa16(&As[0][a0m][a0k*4], A + (size_t)(m0+a0m)*K + a0k*4, p0);
        cpa16(&As[0][a1m][a0k*4], A + (size_t)(m0+a1m)*K + a0k*4, p1);
        cpa16(&Bs[0][b0k][b0n],   B + (size_t)b0k*N + n0 + b0n, true);
        cpa16(&Bs[0][b1k][b0n],   B + (size_t)b1k*N + n0 + b0n, true);
    }
    cpa_commit();

    for (int kt = 0; kt < ntiles; kt++) {
        const int cur = kt & 1;
        if (kt + 1 < ntiles) {
            const int nxt = (kt+1) & 1;
            const int k0 = (kt+1) << 4;
            bool p0 = (m0 + a0m) < M, p1 = (m0 + a1m) < M;
            cpa16(&As[nxt][a0m][a0k*4], A + (size_t)(m0+a0m)*K + k0 + a0k*4, p0);
            cpa16(&As[nxt][a1m][a0k*4], A + (size_t)(m0+a1m)*K + k0 + a0k*4, p1);
            cpa16(&Bs[nxt][b0k][b0n],   B + (size_t)(k0+b0k)*N + n0 + b0n, true);
            cpa16(&Bs[nxt][b1k][b0n],   B + (size_t)(k0+b1k)*N + n0 + b0n, true);
            cpa_commit();
            cpa_wait<1>();
        } else {
            cpa_commit();
            cpa_wait<0>();
        }
        __syncthreads();

        uint32_t ah[4][4], al[4][4], bh[4][2], bl[4][2];
        #pragma unroll
        for (int mt = 0; mt < 4; mt++) {
            const int mr = warpM*64 + mt*16;
            float2 p0 = *(const float2*)&As[cur][mr+g  ][2*tg  ];
            float2 p1 = *(const float2*)&As[cur][mr+g+8][2*tg  ];
            float2 p2 = *(const float2*)&As[cur][mr+g  ][2*tg+8];
            float2 p3 = *(const float2*)&As[cur][mr+g+8][2*tg+8];
            split2(p0.x, p0.y, ah[mt][0], al[mt][0]);
            split2(p1.x, p1.y, ah[mt][1], al[mt][1]);
            split2(p2.x, p2.y, ah[mt][2], al[mt][2]);
            split2(p3.x, p3.y, ah[mt][3], al[mt][3]);
        }
        #pragma unroll
        for (int nt = 0; nt < 4; nt++) {
            const int nc = warpN*32 + nt*8 + g;
            float q0 = Bs[cur][2*tg  ][nc];
            float q1 = Bs[cur][2*tg+1][nc];
            float q2 = Bs[cur][2*tg+8][nc];
            float q3 = Bs[cur][2*tg+9][nc];
            split2(q0, q1, bh[nt][0], bl[nt][0]);
            split2(q2, q3, bh[nt][1], bl[nt][1]);
        }
        #pragma unroll
        for (int mt = 0; mt < 4; mt++)
            #pragma unroll
            for (int nt = 0; nt < 4; nt++) {
                mma_bf16(acc[mt][nt], al[mt], bh[nt]);  // lo*hi
                mma_bf16(acc[mt][nt], ah[mt], bl[nt]);  // hi*lo
                mma_bf16(acc[mt][nt], ah[mt], bh[nt]);  // hi*hi last
            }
        __syncthreads();
    }

    #pragma unroll
    for (int mt = 0; mt < 4; mt++) {
        const int r0 = m0 + warpM*64 + mt*16 + g;
        #pragma unroll
        for (int nt = 0; nt < 4; nt++) {
            const int col = n0 + warpN*32 + nt*8 + tg*2;
            float2 v0 = make_float2(acc[mt][nt][0], acc[mt][nt][1]);
            float2 v1 = make_float2(acc[mt][nt][2], acc[mt][nt][3]);
            if (FUSED) {
                float b0 = bias[col], b1 = bias[col+1];
                v0.x = fmaxf(v0.x + b0, 0.f); v0.y = fmaxf(v0.y + b1, 0.f);
                v1.x = fmaxf(v1.x + b0, 0.f); v1.y = fmaxf(v1.y + b1, 0.f);
            }
            if (r0 < M)     *(float2*)&C[(size_t)r0*N + col]     = v0;
            if (r0 + 8 < M) *(float2*)&C[(size_t)(r0+8)*N + col] = v1;
        }
    }
}

// ---------------- BatchNorm stats (N=128 columns, row-major H) ----------------
__global__ __launch_bounds__(256)
void col_stats(const float* __restrict__ H, int M, float* s1, float* s2)
{
    int c = threadIdx.x & 127;
    int rhalf = threadIdx.x >> 7;
    float a = 0.f, b = 0.f;
    for (int r = blockIdx.x*2 + rhalf; r < M; r += gridDim.x*2) {
        float v = H[(size_t)r*128 + c];
        a += v; b += v*v;
    }
    __shared__ float sa[256], sb[256];
    sa[threadIdx.x]=a; sb[threadIdx.x]=b;
    __syncthreads();
    if (threadIdx.x < 128) {
        atomicAdd(&s1[c], sa[threadIdx.x]+sa[threadIdx.x+128]);
        atomicAdd(&s2[c], sb[threadIdx.x]+sb[threadIdx.x+128]);
    }
}

__global__ void bn_finalize(const float* s1, const float* s2,
                            const float* g, const float* beta,
                            float M, float* scale, float* shift)
{
    int c = threadIdx.x;  // 128
    float mu  = s1[c] / M;
    float var = s2[c] / M - mu*mu;
    float inv = rsqrtf(var + 1e-5f);
    scale[c] = g[c]*inv;
    shift[c] = beta[c] - mu*g[c]*inv;
}

__global__ void bn_apply(const float* __restrict__ H, const float* __restrict__ scale,
                         const float* __restrict__ shift, float* __restrict__ out, int n)
{
    int i = blockIdx.x*blockDim.x + threadIdx.x;
    if (i < n) { int c = i & 127; out[i] = H[i]*scale[c] + shift[c]; }
}

// ---------------- attention-vector fold: wt[k,h] = sum_c W[k, h*128+c]*a[h,c] ----------------
__global__ void att_vec(const float* __restrict__ W /*128x512*/,
                        const float* __restrict__ a /*4x128*/,
                        float* __restrict__ wt /*128x4*/)
{
    __shared__ float sa[512];
    int t = threadIdx.x;            // 128
    *(float4*)&sa[t*4] = *(const float4*)&a[t*4];
    __syncthreads();
    float s0=0.f, s1=0.f, s2=0.f, s3=0.f;
    const float* Wr = W + (size_t)t*512;
    #pragma unroll 4
    for (int c = 0; c < 128; c++) {
        s0 += Wr[c]     * sa[c];
        s1 += Wr[128+c] * sa[128+c];
        s2 += Wr[256+c] * sa[256+c];
        s3 += Wr[384+c] * sa[384+c];
    }
    *(float4*)&wt[t*4] = make_float4(s0, s1, s2, s3);
}

// ---------------- logits GEMV: l[n,h] = sum_k x[n,k]*wt[k,h] ----------------
__global__ __launch_bounds__(256)
void att_gemv(const float* __restrict__ x, const float* __restrict__ wt,
              float* __restrict__ l, int N)
{
    __shared__ float swt[128*4];
    int t = threadIdx.x;
    if (t < 128) *(float4*)&swt[t*4] = *(const float4*)&wt[t*4];
    __syncthreads();
    int warp = t >> 5, lane = t & 31;
    int row = blockIdx.x*8 + warp;
    if (row >= N) return;
    float4 xv = *(const float4*)&x[(size_t)row*128 + lane*4];
    float s0=0.f, s1=0.f, s2=0.f, s3=0.f;
    #pragma unroll
    for (int j = 0; j < 4; j++) {
        float xj = j==0?xv.x : j==1?xv.y : j==2?xv.z : xv.w;
        float4 w = *(const float4*)&swt[(lane*4+j)*4];
        s0 += xj*w.x; s1 += xj*w.y; s2 += xj*w.z; s3 += xj*w.w;
    }
    #pragma unroll
    for (int off=16; off; off>>=1) {
        s0 += __shfl_down_sync(0xffffffff, s0, off);
        s1 += __shfl_down_sync(0xffffffff, s1, off);
        s2 += __shfl_down_sync(0xffffffff, s2, off);
        s3 += __shfl_down_sync(0xffffffff, s3, off);
    }
    if (!lane) *(float4*)&l[(size_t)row*4] = make_float4(s0, s1, s2, s3);
}

// ---------------- CSR build over destination nodes ----------------
__global__ void edge_count(const int* __restrict__ src, const int* __restrict__ dst,
                           int E, int nloop, int* cnt)
{
    int i = blockIdx.x*blockDim.x + threadIdx.x;
    if (i >= E + nloop) return;
    int d;
    if (i < E) { int s = src[i]; d = dst[i]; if (s == d) return; }
    else d = i - E;
    atomicAdd(&cnt[d], 1);
}

__global__ void edge_scatter(const int* __restrict__ src, const int* __restrict__ dst,
                             int E, int nloop, int* wptr, int* elist)
{
    int i = blockIdx.x*blockDim.x + threadIdx.x;
    if (i >= E + nloop) return;
    int s, d;
    if (i < E) { s = src[i]; d = dst[i]; if (s == d) return; }
    else { d = i - E; s = d; }
    int pos = atomicAdd(&wptr[d], 1);
    elist[pos] = s;
}

__global__ __launch_bounds__(1024)
void exscan(const int* __restrict__ cnt, int* __restrict__ rowptr,
            int* __restrict__ wptr, int n)
{
    __shared__ int sums[1024];
    int t = threadIdx.x;
    int chunk = (n + 1023) >> 10;
    int b = t*chunk, e = min(n, b+chunk);
    int s = 0;
    for (int i=b; i<e; i++) s += cnt[i];
    sums[t] = s;
    __syncthreads();
    for (int off=1; off<1024; off<<=1) {
        int v = (t >= off) ? sums[t-off] : 0;
        __syncthreads();
        sums[t] += v;
        __syncthreads();
    }
    int base = (t==0) ? 0 : sums[t-1];
    for (int i=b; i<e; i++) { rowptr[i]=base; wptr[i]=base; base += cnt[i]; }
    if (t == 1023) rowptr[n] = sums[1023];
}

// ---------------- per-dst softmax + gather aggregation ----------------
__global__ __launch_bounds__(128)
void gat_aggregate(const float* __restrict__ xs, const float* __restrict__ ls,
                   const float* __restrict__ ld,
                   const int* __restrict__ rowptr, const int* __restrict__ elist,
                   const float* __restrict__ base, const float* __restrict__ bias,
                   float* __restrict__ out)
{
    int d = blockIdx.x;
    int c = threadIdx.x;  // 128 threads = channel
    int e0 = rowptr[d], e1 = rowptr[d+1];

    __shared__ float sm[4], sdinv[4], sldv[4];
    __shared__ float w[128*4];
    __shared__ int   ssrc[128];

    if (c < 4) {
        float ldh = ld[(size_t)d*4 + c];
        sldv[c] = ldh;
        float mx = -3.0e38f;
        for (int e=e0; e<e1; e++) {
            int s = elist[e];
            float x = ls[(size_t)s*4 + c] + ldh;
            x = (x > 0.f) ? x : 0.2f*x;
            mx = fmaxf(mx, x);
        }
        float den = 0.f;
        for (int e=e0; e<e1; e++) {
            int s = elist[e];
            float x = ls[(size_t)s*4 + c] + ldh;
            x = (x > 0.f) ? x : 0.2f*x;
            den += __expf(x - mx);
        }
        sm[c] = mx;
        sdinv[c] = (e1 > e0) ? (1.f/den) : 0.f;
    }
    __syncthreads();

    float a0=0.f, a1=0.f, a2=0.f, a3=0.f;
    for (int eb=e0; eb<e1; eb+=128) {
        int ne = min(128, e1-eb);
        if (c < ne) ssrc[c] = elist[eb + c];
        __syncthreads();
        for (int t=c; t < ne*4; t += 128) {
            int e = t >> 2, h = t & 3;
            int s = ssrc[e];
            float x = ls[(size_t)s*4 + h] + sldv[h];
            x = (x > 0.f) ? x : 0.2f*x;
            w[t] = __expf(x - sm[h]) * sdinv[h];
        }
        __syncthreads();
        for (int e=0; e<ne; e++) {
            const float* xr = xs + (size_t)ssrc[e]*512;
            float4 ww = *(const float4*)&w[e*4];
            a0 += ww.x * xr[c];
            a1 += ww.y * xr[128+c];
            a2 += ww.z * xr[256+c];
            a3 += ww.w * xr[384+c];
        }
        __syncthreads();
    }
    size_t oi = (size_t)d*128 + c;
    out[oi] = base[oi] + 0.25f*(a0+a1+a2+a3) + bias[c];
}

// ---------------- launch ----------------
extern "C" void kernel_launch(void* const* d_in, const int* in_sizes, int n_in,
                              void* d_out, int out_size)
{
    const float* x_gene = (const float*)d_in[0];
    const float* x_dis  = (const float*)d_in[1];
    const int*   e1s    = (const int*)d_in[2];
    const int*   e1d    = (const int*)d_in[3];
    const int*   e2s    = (const int*)d_in[4];
    const int*   e2d    = (const int*)d_in[5];
    const float* Wg    = (const float*)d_in[6];
    const float* bg    = (const float*)d_in[7];
    const float* gg    = (const float*)d_in[8];
    const float* betag = (const float*)d_in[9];
    const float* Wd    = (const float*)d_in[10];
    const float* bd    = (const float*)d_in[11];
    const float* gd    = (const float*)d_in[12];
    const float* betad = (const float*)d_in[13];
    const float* W1s = (const float*)d_in[14];
    const float* W1d = (const float*)d_in[15];
    const float* a1s = (const float*)d_in[16];
    const float* a1d = (const float*)d_in[17];
    const float* b1  = (const float*)d_in[18];
    const float* W2s = (const float*)d_in[19];
    const float* W2d = (const float*)d_in[20];
    const float* a2s = (const float*)d_in[21];
    const float* a2d = (const float*)d_in[22];
    const float* b2  = (const float*)d_in[23];

    float *Hg,*Hd,*gene,*xs,*ls,*ld,*s1,*s2,*scale,*shift,*wts,*wtd;
    int *cnt,*rowptr,*wptr,*elist;
    cudaGetSymbolAddress((void**)&Hg,    g_Hg);
    cudaGetSymbolAddress((void**)&Hd,    g_Hd);
    cudaGetSymbolAddress((void**)&gene,  g_gene);
    cudaGetSymbolAddress((void**)&xs,    g_xs);
    cudaGetSymbolAddress((void**)&ls,    g_ls);
    cudaGetSymbolAddress((void**)&ld,    g_ld);
    cudaGetSymbolAddress((void**)&s1,    g_s1);
    cudaGetSymbolAddress((void**)&s2,    g_s2);
    cudaGetSymbolAddress((void**)&scale, g_scale);
    cudaGetSymbolAddress((void**)&shift, g_shift);
    cudaGetSymbolAddress((void**)&wts,   g_wt_s);
    cudaGetSymbolAddress((void**)&wtd,   g_wt_d);
    cudaGetSymbolAddress((void**)&cnt,   g_cnt);
    cudaGetSymbolAddress((void**)&rowptr,g_rowptr);
    cudaGetSymbolAddress((void**)&wptr,  g_wptr);
    cudaGetSymbolAddress((void**)&elist, g_elist);

    float* out_gene = (float*)d_out;
    float* out_dis  = (float*)d_out + (size_t)NGENE*CDIM;

    // ---- encoders: h = relu(x@W + b) ----
    tgemm<1><<<dim3(1, (NGENE+127)/128), 256>>>(x_gene, Wg, bg, Hg, NGENE, 128, 512);
    tgemm<1><<<dim3(1, (NDIS +127)/128), 256>>>(x_dis,  Wd, bd, Hd, NDIS,  128, 256);

    // BN gene
    zero_f<<<1,128>>>(s1, CDIM);
    zero_f<<<1,128>>>(s2, CDIM);
    col_stats<<<256,256>>>(Hg, NGENE, s1, s2);
    bn_finalize<<<1,128>>>(s1, s2, gg, betag, (float)NGENE, scale, shift);
    bn_apply<<<(NGENE*CDIM+255)/256,256>>>(Hg, scale, shift, gene, NGENE*CDIM);
    // BN dis -> directly into output dis region (also GAT1 src features)
    zero_f<<<1,128>>>(s1, CDIM);
    zero_f<<<1,128>>>(s2, CDIM);
    col_stats<<<256,256>>>(Hd, NDIS, s1, s2);
    bn_finalize<<<1,128>>>(s1, s2, gd, betad, (float)NDIS, scale, shift);
    bn_apply<<<(NDIS*CDIM+255)/256,256>>>(Hd, scale, shift, out_dis, NDIS*CDIM);

    // ---- GAT relation 1: dis -> gene ----
    tgemm<0><<<dim3(4, (NDIS +127)/128), 256>>>(out_dis, W1s, nullptr, xs, NDIS,  512, 128);
    att_vec<<<1,128>>>(W1s, a1s, wts);
    att_vec<<<1,128>>>(W1d, a1d, wtd);
    att_gemv<<<(NDIS +7)/8, 256>>>(out_dis, wts, ls, NDIS);
    att_gemv<<<(NGENE+7)/8, 256>>>(gene,    wtd, ld, NGENE);
    zero_i<<<(NGENE+255)/256,256>>>(cnt, NGENE);
    edge_count  <<<(E1N+NDIS+255)/256,256>>>(e1s, e1d, E1N, NDIS, cnt);
    exscan<<<1,1024>>>(cnt, rowptr, wptr, NGENE);
    edge_scatter<<<(E1N+NDIS+255)/256,256>>>(e1s, e1d, E1N, NDIS, wptr, elist);
    gat_aggregate<<<NGENE,128>>>(xs, ls, ld, rowptr, elist, gene, b1, gene);

    // ---- GAT relation 2: gene -> gene (updated gene) ----
    tgemm<0><<<dim3(4, (NGENE+127)/128), 256>>>(gene, W2s, nullptr, xs, NGENE, 512, 128);
    att_vec<<<1,128>>>(W2s, a2s, wts);
    att_vec<<<1,128>>>(W2d, a2d, wtd);
    att_gemv<<<(NGENE+7)/8, 256>>>(gene, wts, ls, NGENE);
    att_gemv<<<(NGENE+7)/8, 256>>>(gene, wtd, ld, NGENE);
    zero_i<<<(NGENE+255)/256,256>>>(cnt, NGENE);
    edge_count  <<<(E2N+NGENE+255)/256,256>>>(e2s, e2d, E2N, NGENE, cnt);
    exscan<<<1,1024>>>(cnt, rowptr, wptr, NGENE);
    edge_scatter<<<(E2N+NGENE+255)/256,256>>>(e2s, e2d, E2N, NGENE, wptr, elist);
    gat_aggregate<<<NGENE,128>>>(xs, ls, ld, rowptr, elist, gene, b2, out_gene);
}

// round 9
// speedup vs baseline: 3.5443x; 1.9004x over previous
#include <cuda_runtime.h>
#include <math.h>
#include <float.h>
#include <stdint.h>

#define NGENE 50000
#define NDIS  25000
#define E1N   150000
#define E2N   150000
#define CDIM  128
#define HC    512   /* H_HEADS * C_HID */

// ---------------- scratch (static __device__ — no allocation) ----------------
__device__ float g_Hg[NGENE*CDIM];
__device__ float g_Hd[NDIS*CDIM];
__device__ float g_gene[NGENE*CDIM];
__device__ float g_xs[NGENE*HC];
__device__ float g_ls1[NGENE*4];
__device__ float g_ld1[NGENE*4];
__device__ float g_ls2[NGENE*4];
__device__ float g_ld2[NGENE*4];
__device__ float g_partg[256*256];
__device__ float g_partd[256*256];
__device__ float g_scaleg[CDIM];
__device__ float g_shiftg[CDIM];
__device__ float g_scaled[CDIM];
__device__ float g_shiftd[CDIM];
__device__ float g_wts1[CDIM*4];
__device__ float g_wtd1[CDIM*4];
__device__ float g_wts2[CDIM*4];
__device__ float g_wtd2[CDIM*4];
__device__ int   g_cnt1[NGENE];
__device__ int   g_cnt2[NGENE];
__device__ int   g_rowptr1[NGENE+1];
__device__ int   g_rowptr2[NGENE+1];
__device__ int   g_wptr1[NGENE];
__device__ int   g_wptr2[NGENE];
__device__ int   g_elist1[E1N+NDIS];
__device__ int   g_elist2[E2N+NGENE];

// ---------------- streams/events created before harness checkpoints ----------------
struct GraphCtx {
    cudaStream_t sB, sC;
    cudaEvent_t ev0, evC0, evCsr1, evCsr2, evB;
    GraphCtx() {
        cudaStreamCreateWithFlags(&sB, cudaStreamNonBlocking);
        cudaStreamCreateWithFlags(&sC, cudaStreamNonBlocking);
        cudaEventCreateWithFlags(&ev0,    cudaEventDisableTiming);
        cudaEventCreateWithFlags(&evC0,   cudaEventDisableTiming);
        cudaEventCreateWithFlags(&evCsr1, cudaEventDisableTiming);
        cudaEventCreateWithFlags(&evCsr2, cudaEventDisableTiming);
        cudaEventCreateWithFlags(&evB,    cudaEventDisableTiming);
    }
};
static GraphCtx g_ctx;

// ---------------- utility ----------------
__global__ void zero2_i(int* p, int* q, int n){
    int i = blockIdx.x*blockDim.x+threadIdx.x;
    if(i<n){ p[i]=0; q[i]=0; }
}

// ---------------- bf16 3-product tensor-core GEMM (near-fp32 accurate) ----------------
__device__ __forceinline__ void cpa16(void* dst, const void* src, bool pred) {
    uint32_t d = (uint32_t)__cvta_generic_to_shared(dst);
    int sz = pred ? 16 : 0;
    asm volatile("cp.async.cg.shared.global [%0], [%1], 16, %2;\n"
                 :: "r"(d), "l"(src), "r"(sz));
}
__device__ __forceinline__ void cpa_commit() {
    asm volatile("cp.async.commit_group;\n" ::: "memory");
}
template<int NWAIT>
__device__ __forceinline__ void cpa_wait() {
    asm volatile("cp.async.wait_group %0;\n" :: "n"(NWAIT) : "memory");
}
__device__ __forceinline__ void split2(float x0, float x1, uint32_t& hi, uint32_t& lo) {
    uint32_t h;
    asm("cvt.rn.bf16x2.f32 %0, %1, %2;" : "=r"(h) : "f"(x1), "f"(x0));
    float r0 = x0 - __uint_as_float(h << 16);
    float r1 = x1 - __uint_as_float(h & 0xffff0000u);
    uint32_t l;
    asm("cvt.rn.bf16x2.f32 %0, %1, %2;" : "=r"(l) : "f"(r1), "f"(r0));
    hi = h; lo = l;
}
__device__ __forceinline__ void mma_bf16(float* c, const uint32_t* a, const uint32_t* b) {
    asm volatile(
        "mma.sync.aligned.m16n8k16.row.col.f32.bf16.bf16.f32 "
        "{%0,%1,%2,%3}, {%4,%5,%6,%7}, {%8,%9}, {%0,%1,%2,%3};\n"
        : "+f"(c[0]), "+f"(c[1]), "+f"(c[2]), "+f"(c[3])
        : "r"(a[0]), "r"(a[1]), "r"(a[2]), "r"(a[3]), "r"(b[0]), "r"(b[1]));
}

template<int FUSED>
__global__ __launch_bounds__(256)
void tgemm(const float* __restrict__ A, const float* __restrict__ B,
           const float* __restrict__ bias, float* __restrict__ C,
           int M, int N, int K)
{
    __shared__ float As[2][128][20];
    __shared__ float Bs[2][16][132];

    const int t = threadIdx.x;
    const int lane = t & 31, warp = t >> 5;
    const int g = lane >> 2, tg = lane & 3;
    const int warpM = warp >> 2, warpN = warp & 3;   // 2 x 4 warps
    const int m0 = blockIdx.y * 128, n0 = blockIdx.x * 128;

    float acc[4][4][4];
    #pragma unroll
    for (int mt=0; mt<4; mt++)
        #pragma unroll
        for (int nt=0; nt<4; nt++)
            #pragma unroll
            for (int i=0; i<4; i++) acc[mt][nt][i] = 0.f;

    const int ntiles = K >> 4;

    const int a0m = t >> 2,        a0k = t & 3;
    const int a1m = (t+256) >> 2;
    const int b0k = t >> 5,        b0n = (t & 31) * 4;
    const int b1k = (t+256) >> 5;

    {
        bool p0 = (m0 + a0m) < M, p1 = (m0 + a1m) < M;
        cpa16(&As[0][a0m][a0k*4], A + (size_t)(m0+a0m)*K + a0k*4, p0);
        cpa16(&As[0][a1m][a0k*4], A + (size_t)(m0+a1m)*K + a0k*4, p1);
        cpa16(&Bs[0][b0k][b0n],   B + (size_t)b0k*N + n0 + b0n, true);
        cpa16(&Bs[0][b1k][b0n],   B + (size_t)b1k*N + n0 + b0n, true);
    }
    cpa_commit();

    for (int kt = 0; kt < ntiles; kt++) {
        const int cur = kt & 1;
        if (kt + 1 < ntiles) {
            const int nxt = (kt+1) & 1;
            const int k0 = (kt+1) << 4;
            bool p0 = (m0 + a0m) < M, p1 = (m0 + a1m) < M;
            cpa16(&As[nxt][a0m][a0k*4], A + (size_t)(m0+a0m)*K + k0 + a0k*4, p0);
            cpa16(&As[nxt][a1m][a0k*4], A + (size_t)(m0+a1m)*K + k0 + a0k*4, p1);
            cpa16(&Bs[nxt][b0k][b0n],   B + (size_t)(k0+b0k)*N + n0 + b0n, true);
            cpa16(&Bs[nxt][b1k][b0n],   B + (size_t)(k0+b1k)*N + n0 + b0n, true);
            cpa_commit();
            cpa_wait<1>();
        } else {
            cpa_commit();
            cpa_wait<0>();
        }
        __syncthreads();

        uint32_t ah[4][4], al[4][4], bh[4][2], bl[4][2];
        #pragma unroll
        for (int mt = 0; mt < 4; mt++) {
            const int mr = warpM*64 + mt*16;
            float2 p0 = *(const float2*)&As[cur][mr+g  ][2*tg  ];
            float2 p1 = *(const float2*)&As[cur][mr+g+8][2*tg  ];
            float2 p2 = *(const float2*)&As[cur][mr+g  ][2*tg+8];
            float2 p3 = *(const float2*)&As[cur][mr+g+8][2*tg+8];
            split2(p0.x, p0.y, ah[mt][0], al[mt][0]);
            split2(p1.x, p1.y, ah[mt][1], al[mt][1]);
            split2(p2.x, p2.y, ah[mt][2], al[mt][2]);
            split2(p3.x, p3.y, ah[mt][3], al[mt][3]);
        }
        #pragma unroll
        for (int nt = 0; nt < 4; nt++) {
            const int nc = warpN*32 + nt*8 + g;
            float q0 = Bs[cur][2*tg  ][nc];
            float q1 = Bs[cur][2*tg+1][nc];
            float q2 = Bs[cur][2*tg+8][nc];
            float q3 = Bs[cur][2*tg+9][nc];
            split2(q0, q1, bh[nt][0], bl[nt][0]);
            split2(q2, q3, bh[nt][1], bl[nt][1]);
        }
        #pragma unroll
        for (int mt = 0; mt < 4; mt++)
            #pragma unroll
            for (int nt = 0; nt < 4; nt++) {
                mma_bf16(acc[mt][nt], al[mt], bh[nt]);
                mma_bf16(acc[mt][nt], ah[mt], bl[nt]);
                mma_bf16(acc[mt][nt], ah[mt], bh[nt]);
            }
        __syncthreads();
    }

    #pragma unroll
    for (int mt = 0; mt < 4; mt++) {
        const int r0 = m0 + warpM*64 + mt*16 + g;
        #pragma unroll
        for (int nt = 0; nt < 4; nt++) {
            const int col = n0 + warpN*32 + nt*8 + tg*2;
            float2 v0 = make_float2(acc[mt][nt][0], acc[mt][nt][1]);
            float2 v1 = make_float2(acc[mt][nt][2], acc[mt][nt][3]);
            if (FUSED) {
                float b0 = bias[col], b1 = bias[col+1];
                v0.x = fmaxf(v0.x + b0, 0.f); v0.y = fmaxf(v0.y + b1, 0.f);
                v1.x = fmaxf(v1.x + b0, 0.f); v1.y = fmaxf(v1.y + b1, 0.f);
            }
            if (r0 < M)     *(float2*)&C[(size_t)r0*N + col]     = v0;
            if (r0 + 8 < M) *(float2*)&C[(size_t)(r0+8)*N + col] = v1;
        }
    }
}

// ---------------- BatchNorm stats: per-block partials (no atomics, no zeroing) ----------------
__global__ __launch_bounds__(256)
void col_stats_part(const float* __restrict__ H, int M, float* __restrict__ part)
{
    int c = threadIdx.x & 127;
    int rhalf = threadIdx.x >> 7;
    float a = 0.f, b = 0.f;
    for (int r = blockIdx.x*2 + rhalf; r < M; r += gridDim.x*2) {
        float v = H[(size_t)r*128 + c];
        a += v; b += v*v;
    }
    __shared__ float sa[256], sb[256];
    sa[threadIdx.x]=a; sb[threadIdx.x]=b;
    __syncthreads();
    if (threadIdx.x < 128) {
        part[blockIdx.x*256 + c]       = sa[c]+sa[c+128];
        part[blockIdx.x*256 + 128 + c] = sb[c]+sb[c+128];
    }
}

__global__ void bn_finalize2(const float* __restrict__ part,
                             const float* g, const float* beta,
                             float M, float* scale, float* shift)
{
    int c = threadIdx.x;  // 128
    float s1 = 0.f, s2 = 0.f;
    #pragma unroll 4
    for (int b = 0; b < 256; b++) {
        s1 += part[b*256 + c];
        s2 += part[b*256 + 128 + c];
    }
    float mu  = s1 / M;
    float var = s2 / M - mu*mu;
    float inv = rsqrtf(var + 1e-5f);
    scale[c] = g[c]*inv;
    shift[c] = beta[c] - mu*g[c]*inv;
}

// ---------------- fused BN-apply + logits GEMV ----------------
// out[row] = H[row]*scale+shift ; l[row,h] = sum_k out[row,k]*wt[k,h]
__global__ __launch_bounds__(256)
void bn_apply_gemv(const float* __restrict__ H, const float* __restrict__ scale,
                   const float* __restrict__ shift, const float* __restrict__ wt,
                   float* __restrict__ out, float* __restrict__ l, int N)
{
    __shared__ float swt[512], ssc[128], ssh[128];
    int t = threadIdx.x;
    if (t < 128) {
        *(float4*)&swt[t*4] = *(const float4*)&wt[t*4];
        ssc[t] = scale[t]; ssh[t] = shift[t];
    }
    __syncthreads();
    int warp = t >> 5, lane = t & 31;
    int row = blockIdx.x*8 + warp;
    if (row >= N) return;
    float4 hv = *(const float4*)&H[(size_t)row*128 + lane*4];
    float4 ov;
    ov.x = hv.x*ssc[lane*4+0] + ssh[lane*4+0];
    ov.y = hv.y*ssc[lane*4+1] + ssh[lane*4+1];
    ov.z = hv.z*ssc[lane*4+2] + ssh[lane*4+2];
    ov.w = hv.w*ssc[lane*4+3] + ssh[lane*4+3];
    *(float4*)&out[(size_t)row*128 + lane*4] = ov;
    float s0=0.f, s1=0.f, s2=0.f, s3=0.f;
    #pragma unroll
    for (int j = 0; j < 4; j++) {
        float xj = j==0?ov.x : j==1?ov.y : j==2?ov.z : ov.w;
        float4 w = *(const float4*)&swt[(lane*4+j)*4];
        s0 += xj*w.x; s1 += xj*w.y; s2 += xj*w.z; s3 += xj*w.w;
    }
    #pragma unroll
    for (int off=16; off; off>>=1) {
        s0 += __shfl_down_sync(0xffffffff, s0, off);
        s1 += __shfl_down_sync(0xffffffff, s1, off);
        s2 += __shfl_down_sync(0xffffffff, s2, off);
        s3 += __shfl_down_sync(0xffffffff, s3, off);
    }
    if (!lane) *(float4*)&l[(size_t)row*4] = make_float4(s0, s1, s2, s3);
}

// ---------------- attention-vector folds (all 4 in one launch) ----------------
__global__ void att_vec_all(const float* W1, const float* a1, float* o1,
                            const float* W2, const float* a2, float* o2,
                            const float* W3, const float* a3, float* o3,
                            const float* W4, const float* a4, float* o4)
{
    const float* W; const float* a; float* o;
    switch (blockIdx.x) {
        case 0: W=W1; a=a1; o=o1; break;
        case 1: W=W2; a=a2; o=o2; break;
        case 2: W=W3; a=a3; o=o3; break;
        default: W=W4; a=a4; o=o4; break;
    }
    __shared__ float sa[512];
    int t = threadIdx.x;            // 128
    *(float4*)&sa[t*4] = *(const float4*)&a[t*4];
    __syncthreads();
    float s0=0.f, s1=0.f, s2=0.f, s3=0.f;
    const float* Wr = W + (size_t)t*512;
    #pragma unroll 4
    for (int c = 0; c < 128; c++) {
        s0 += Wr[c]     * sa[c];
        s1 += Wr[128+c] * sa[128+c];
        s2 += Wr[256+c] * sa[256+c];
        s3 += Wr[384+c] * sa[384+c];
    }
    *(float4*)&o[t*4] = make_float4(s0, s1, s2, s3);
}

// ---------------- CSR build over destination nodes ----------------
__global__ void edge_count(const int* __restrict__ src, const int* __restrict__ dst,
                           int E, int nloop, int* cnt)
{
    int i = blockIdx.x*blockDim.x + threadIdx.x;
    if (i >= E + nloop) return;
    int d;
    if (i < E) { int s = src[i]; d = dst[i]; if (s == d) return; }
    else d = i - E;
    atomicAdd(&cnt[d], 1);
}

__global__ void edge_scatter(const int* __restrict__ src, const int* __restrict__ dst,
                             int E, int nloop, int* wptr, int* elist)
{
    int i = blockIdx.x*blockDim.x + threadIdx.x;
    if (i >= E + nloop) return;
    int s, d;
    if (i < E) { s = src[i]; d = dst[i]; if (s == d) return; }
    else { d = i - E; s = d; }
    int pos = atomicAdd(&wptr[d], 1);
    elist[pos] = s;
}

__global__ __launch_bounds__(1024)
void exscan(const int* __restrict__ cnt, int* __restrict__ rowptr,
            int* __restrict__ wptr, int n)
{
    __shared__ int sums[1024];
    int t = threadIdx.x;
    int chunk = (n + 1023) >> 10;
    int b = t*chunk, e = min(n, b+chunk);
    int s = 0;
    for (int i=b; i<e; i++) s += cnt[i];
    sums[t] = s;
    __syncthreads();
    for (int off=1; off<1024; off<<=1) {
        int v = (t >= off) ? sums[t-off] : 0;
        __syncthreads();
        sums[t] += v;
        __syncthreads();
    }
    int base = (t==0) ? 0 : sums[t-1];
    for (int i=b; i<e; i++) { rowptr[i]=base; wptr[i]=base; base += cnt[i]; }
    if (t == 1023) rowptr[n] = sums[1023];
}

// ---------------- per-dst softmax + gather aggregation (+optional fused logits) ----------------
__global__ __launch_bounds__(128)
void gat_aggregate(const float* __restrict__ xs, const float* __restrict__ ls,
                   const float* __restrict__ ld,
                   const int* __restrict__ rowptr, const int* __restrict__ elist,
                   const float* __restrict__ base, const float* __restrict__ bias,
                   float* __restrict__ out,
                   const float* __restrict__ nwts, const float* __restrict__ nwtd,
                   float* __restrict__ lsout, float* __restrict__ ldout)
{
    int d = blockIdx.x;
    int c = threadIdx.x;  // 128 threads = channel
    int e0 = rowptr[d], e1 = rowptr[d+1];

    __shared__ float sm[4], sdinv[4], sldv[4];
    __shared__ float w[128*4];
    __shared__ int   ssrc[128];
    __shared__ float sws[512], swd[512], sv[128];

    if (lsout) {
        *(float4*)&sws[c*4] = *(const float4*)&nwts[c*4];
        *(float4*)&swd[c*4] = *(const float4*)&nwtd[c*4];
    }

    if (c < 4) {
        float ldh = ld[(size_t)d*4 + c];
        sldv[c] = ldh;
        float mx = -3.0e38f;
        for (int e=e0; e<e1; e++) {
            int s = elist[e];
            float x = ls[(size_t)s*4 + c] + ldh;
            x = (x > 0.f) ? x : 0.2f*x;
            mx = fmaxf(mx, x);
        }
        float den = 0.f;
        for (int e=e0; e<e1; e++) {
            int s = elist[e];
            float x = ls[(size_t)s*4 + c] + ldh;
            x = (x > 0.f) ? x : 0.2f*x;
            den += __expf(x - mx);
        }
        sm[c] = mx;
        sdinv[c] = (e1 > e0) ? (1.f/den) : 0.f;
    }
    __syncthreads();

    float a0=0.f, a1=0.f, a2=0.f, a3=0.f;
    for (int eb=e0; eb<e1; eb+=128) {
        int ne = min(128, e1-eb);
        if (c < ne) ssrc[c] = elist[eb + c];
        __syncthreads();
        for (int t=c; t < ne*4; t += 128) {
            int e = t >> 2, h = t & 3;
            int s = ssrc[e];
            float x = ls[(size_t)s*4 + h] + sldv[h];
            x = (x > 0.f) ? x : 0.2f*x;
            w[t] = __expf(x - sm[h]) * sdinv[h];
        }
        __syncthreads();
        for (int e=0; e<ne; e++) {
            const float* xr = xs + (size_t)ssrc[e]*512;
            float4 ww = *(const float4*)&w[e*4];
            a0 += ww.x * xr[c];
            a1 += ww.y * xr[128+c];
            a2 += ww.z * xr[256+c];
            a3 += ww.w * xr[384+c];
        }
        __syncthreads();
    }
    size_t oi = (size_t)d*128 + c;
    float v = base[oi] + 0.25f*(a0+a1+a2+a3) + bias[c];
    out[oi] = v;

    if (lsout) {
        sv[c] = v;
        __syncthreads();
        if (c < 32) {
            float ps[4] = {0,0,0,0}, pd[4] = {0,0,0,0};
            #pragma unroll
            for (int j = 0; j < 4; j++) {
                int cc = c + j*32;
                float vv = sv[cc];
                #pragma unroll
                for (int h = 0; h < 4; h++) {
                    ps[h] += vv * sws[cc*4 + h];
                    pd[h] += vv * swd[cc*4 + h];
                }
            }
            #pragma unroll
            for (int off=16; off; off>>=1) {
                #pragma unroll
                for (int h = 0; h < 4; h++) {
                    ps[h] += __shfl_down_sync(0xffffffff, ps[h], off);
                    pd[h] += __shfl_down_sync(0xffffffff, pd[h], off);
                }
            }
            if (c == 0) {
                *(float4*)&lsout[(size_t)d*4] = make_float4(ps[0], ps[1], ps[2], ps[3]);
                *(float4*)&ldout[(size_t)d*4] = make_float4(pd[0], pd[1], pd[2], pd[3]);
            }
        }
    }
}

// ---------------- launch ----------------
extern "C" void kernel_launch(void* const* d_in, const int* in_sizes, int n_in,
                              void* d_out, int out_size)
{
    const float* x_gene = (const float*)d_in[0];
    const float* x_dis  = (const float*)d_in[1];
    const int*   e1s    = (const int*)d_in[2];
    const int*   e1d    = (const int*)d_in[3];
    const int*   e2s    = (const int*)d_in[4];
    const int*   e2d    = (const int*)d_in[5];
    const float* Wg    = (const float*)d_in[6];
    const float* bg    = (const float*)d_in[7];
    const float* gg    = (const float*)d_in[8];
    const float* betag = (const float*)d_in[9];
    const float* Wd    = (const float*)d_in[10];
    const float* bd    = (const float*)d_in[11];
    const float* gd    = (const float*)d_in[12];
    const float* betad = (const float*)d_in[13];
    const float* W1s = (const float*)d_in[14];
    const float* W1d = (const float*)d_in[15];
    const float* a1s = (const float*)d_in[16];
    const float* a1d = (const float*)d_in[17];
    const float* b1  = (const float*)d_in[18];
    const float* W2s = (const float*)d_in[19];
    const float* W2d = (const float*)d_in[20];
    const float* a2s = (const float*)d_in[21];
    const float* a2d = (const float*)d_in[22];
    const float* b2  = (const float*)d_in[23];

    float *Hg,*Hd,*gene,*xs,*ls1,*ld1,*ls2,*ld2,*partg,*partd;
    float *scaleg,*shiftg,*scaled,*shiftd,*wts1,*wtd1,*wts2,*wtd2;
    int *cnt1,*cnt2,*rowptr1,*rowptr2,*wptr1,*wptr2,*elist1,*elist2;
    cudaGetSymbolAddress((void**)&Hg,    g_Hg);
    cudaGetSymbolAddress((void**)&Hd,    g_Hd);
    cudaGetSymbolAddress((void**)&gene,  g_gene);
    cudaGetSymbolAddress((void**)&xs,    g_xs);
    cudaGetSymbolAddress((void**)&ls1,   g_ls1);
    cudaGetSymbolAddress((void**)&ld1,   g_ld1);
    cudaGetSymbolAddress((void**)&ls2,   g_ls2);
    cudaGetSymbolAddress((void**)&ld2,   g_ld2);
    cudaGetSymbolAddress((void**)&partg, g_partg);
    cudaGetSymbolAddress((void**)&partd, g_partd);
    cudaGetSymbolAddress((void**)&scaleg,g_scaleg);
    cudaGetSymbolAddress((void**)&shiftg,g_shiftg);
    cudaGetSymbolAddress((void**)&scaled,g_scaled);
    cudaGetSymbolAddress((void**)&shiftd,g_shiftd);
    cudaGetSymbolAddress((void**)&wts1,  g_wts1);
    cudaGetSymbolAddress((void**)&wtd1,  g_wtd1);
    cudaGetSymbolAddress((void**)&wts2,  g_wts2);
    cudaGetSymbolAddress((void**)&wtd2,  g_wtd2);
    cudaGetSymbolAddress((void**)&cnt1,  g_cnt1);
    cudaGetSymbolAddress((void**)&cnt2,  g_cnt2);
    cudaGetSymbolAddress((void**)&rowptr1,g_rowptr1);
    cudaGetSymbolAddress((void**)&rowptr2,g_rowptr2);
    cudaGetSymbolAddress((void**)&wptr1, g_wptr1);
    cudaGetSymbolAddress((void**)&wptr2, g_wptr2);
    cudaGetSymbolAddress((void**)&elist1,g_elist1);
    cudaGetSymbolAddress((void**)&elist2,g_elist2);

    float* out_gene = (float*)d_out;
    float* out_dis  = (float*)d_out + (size_t)NGENE*CDIM;

    cudaStream_t sB = g_ctx.sB, sC = g_ctx.sC;

    // fork
    cudaEventRecord(g_ctx.ev0, 0);
    cudaStreamWaitEvent(sB, g_ctx.ev0, 0);
    cudaStreamWaitEvent(sC, g_ctx.ev0, 0);

    // ---- stream C: attention-vector folds + CSR builds (feature-independent) ----
    att_vec_all<<<4,128,0,sC>>>(W1s,a1s,wts1, W1d,a1d,wtd1, W2s,a2s,wts2, W2d,a2d,wtd2);
    cudaEventRecord(g_ctx.evC0, sC);
    zero2_i<<<(NGENE+255)/256,256,0,sC>>>(cnt1, cnt2, NGENE);
    edge_count  <<<(E1N+NDIS+255)/256,256,0,sC>>>(e1s, e1d, E1N, NDIS, cnt1);
    exscan<<<1,1024,0,sC>>>(cnt1, rowptr1, wptr1, NGENE);
    edge_scatter<<<(E1N+NDIS+255)/256,256,0,sC>>>(e1s, e1d, E1N, NDIS, wptr1, elist1);
    cudaEventRecord(g_ctx.evCsr1, sC);
    edge_count  <<<(E2N+NGENE+255)/256,256,0,sC>>>(e2s, e2d, E2N, NGENE, cnt2);
    exscan<<<1,1024,0,sC>>>(cnt2, rowptr2, wptr2, NGENE);
    edge_scatter<<<(E2N+NGENE+255)/256,256,0,sC>>>(e2s, e2d, E2N, NGENE, wptr2, elist2);
    cudaEventRecord(g_ctx.evCsr2, sC);

    // ---- stream B: dis encoder -> BN(+ls1 gemv) -> xs1 GEMM ----
    tgemm<1><<<dim3(1, (NDIS+127)/128), 256, 0, sB>>>(x_dis, Wd, bd, Hd, NDIS, 128, 256);
    col_stats_part<<<256,256,0,sB>>>(Hd, NDIS, partd);
    bn_finalize2<<<1,128,0,sB>>>(partd, gd, betad, (float)NDIS, scaled, shiftd);
    cudaStreamWaitEvent(sB, g_ctx.evC0, 0);
    bn_apply_gemv<<<(NDIS+7)/8,256,0,sB>>>(Hd, scaled, shiftd, wts1, out_dis, ls1, NDIS);
    tgemm<0><<<dim3(4, (NDIS+127)/128), 256, 0, sB>>>(out_dis, W1s, nullptr, xs, NDIS, 512, 128);
    cudaEventRecord(g_ctx.evB, sB);

    // ---- stream 0 (main): gene encoder -> BN(+ld1 gemv) -> agg1 -> xs2 -> agg2 ----
    tgemm<1><<<dim3(1, (NGENE+127)/128), 256>>>(x_gene, Wg, bg, Hg, NGENE, 128, 512);
    col_stats_part<<<256,256>>>(Hg, NGENE, partg);
    bn_finalize2<<<1,128>>>(partg, gg, betag, (float)NGENE, scaleg, shiftg);
    cudaStreamWaitEvent(0, g_ctx.evC0, 0);
    bn_apply_gemv<<<(NGENE+7)/8,256>>>(Hg, scaleg, shiftg, wtd1, gene, ld1, NGENE);
    cudaStreamWaitEvent(0, g_ctx.evB, 0);
    cudaStreamWaitEvent(0, g_ctx.evCsr1, 0);
    gat_aggregate<<<NGENE,128>>>(xs, ls1, ld1, rowptr1, elist1, gene, b1, gene,
                                 wts2, wtd2, ls2, ld2);
    tgemm<0><<<dim3(4, (NGENE+127)/128), 256>>>(gene, W2s, nullptr, xs, NGENE, 512, 128);
    cudaStreamWaitEvent(0, g_ctx.evCsr2, 0);
    gat_aggregate<<<NGENE,128>>>(xs, ls2, ld2, rowptr2, elist2, gene, b2, out_gene,
                                 nullptr, nullptr, nullptr, nullptr);
}

// round 10
// speedup vs baseline: 3.5939x; 1.0140x over previous
#include <cuda_runtime.h>
#include <math.h>
#include <float.h>
#include <stdint.h>

#define NGENE 50000
#define NDIS  25000
#define E1N   150000
#define E2N   150000
#define CDIM  128
#define HC    512   /* H_HEADS * C_HID */
#define NBG   391   /* ceil(NGENE/128) */
#define NBD   196   /* ceil(NDIS/128)  */

// ---------------- scratch (static __device__ — no allocation) ----------------
__device__ float g_Hg[NGENE*CDIM];
__device__ float g_Hd[NDIS*CDIM];
__device__ float g_gene[NGENE*CDIM];
__device__ float g_xs[NGENE*HC];
__device__ float g_ls1[NGENE*4];
__device__ float g_ld1[NGENE*4];
__device__ float g_ls2[NGENE*4];
__device__ float g_ld2[NGENE*4];
__device__ float g_partg[NBG*256];
__device__ float g_partd[NBD*256];
__device__ float g_scaleg[CDIM];
__device__ float g_shiftg[CDIM];
__device__ float g_scaled[CDIM];
__device__ float g_shiftd[CDIM];
__device__ float g_wts1[CDIM*4];
__device__ float g_wtd1[CDIM*4];
__device__ float g_wts2[CDIM*4];
__device__ float g_wtd2[CDIM*4];
__device__ int   g_cnt1[NGENE];
__device__ int   g_cnt2[NGENE];
__device__ int   g_rowptr1[NGENE+1];
__device__ int   g_rowptr2[NGENE+1];
__device__ int   g_wptr1[NGENE];
__device__ int   g_wptr2[NGENE];
__device__ int   g_elist1[E1N+NDIS];
__device__ int   g_elist2[E2N+NGENE];

// ---------------- streams/events created before harness checkpoints ----------------
struct GraphCtx {
    cudaStream_t sB, sC;
    cudaEvent_t ev0, evC0, evCsr, evB;
    GraphCtx() {
        cudaStreamCreateWithFlags(&sB, cudaStreamNonBlocking);
        cudaStreamCreateWithFlags(&sC, cudaStreamNonBlocking);
        cudaEventCreateWithFlags(&ev0,  cudaEventDisableTiming);
        cudaEventCreateWithFlags(&evC0, cudaEventDisableTiming);
        cudaEventCreateWithFlags(&evCsr,cudaEventDisableTiming);
        cudaEventCreateWithFlags(&evB,  cudaEventDisableTiming);
    }
};
static GraphCtx g_ctx;

// ---------------- utility ----------------
__global__ void zero2_i(int* p, int* q, int n){
    int i = blockIdx.x*blockDim.x+threadIdx.x;
    if(i<n){ p[i]=0; q[i]=0; }
}

// ---------------- bf16 3-product tensor-core GEMM (near-fp32 accurate) ----------------
__device__ __forceinline__ void cpa16(void* dst, const void* src, bool pred) {
    uint32_t d = (uint32_t)__cvta_generic_to_shared(dst);
    int sz = pred ? 16 : 0;
    asm volatile("cp.async.cg.shared.global [%0], [%1], 16, %2;\n"
                 :: "r"(d), "l"(src), "r"(sz));
}
__device__ __forceinline__ void cpa_commit() {
    asm volatile("cp.async.commit_group;\n" ::: "memory");
}
template<int NWAIT>
__device__ __forceinline__ void cpa_wait() {
    asm volatile("cp.async.wait_group %0;\n" :: "n"(NWAIT) : "memory");
}
__device__ __forceinline__ void split2(float x0, float x1, uint32_t& hi, uint32_t& lo) {
    uint32_t h;
    asm("cvt.rn.bf16x2.f32 %0, %1, %2;" : "=r"(h) : "f"(x1), "f"(x0));
    float r0 = x0 - __uint_as_float(h << 16);
    float r1 = x1 - __uint_as_float(h & 0xffff0000u);
    uint32_t l;
    asm("cvt.rn.bf16x2.f32 %0, %1, %2;" : "=r"(l) : "f"(r1), "f"(r0));
    hi = h; lo = l;
}
__device__ __forceinline__ void mma_bf16(float* c, const uint32_t* a, const uint32_t* b) {
    asm volatile(
        "mma.sync.aligned.m16n8k16.row.col.f32.bf16.bf16.f32 "
        "{%0,%1,%2,%3}, {%4,%5,%6,%7}, {%8,%9}, {%0,%1,%2,%3};\n"
        : "+f"(c[0]), "+f"(c[1]), "+f"(c[2]), "+f"(c[3])
        : "r"(a[0]), "r"(a[1]), "r"(a[2]), "r"(a[3]), "r"(b[0]), "r"(b[1]));
}

// FUSED=1: +bias, relu, and per-block column sum/sumsq partials -> part[by*256 + {c,128+c}]
template<int FUSED>
__global__ __launch_bounds__(256)
void tgemm(const float* __restrict__ A, const float* __restrict__ B,
           const float* __restrict__ bias, float* __restrict__ C,
           int M, int N, int K, float* __restrict__ part)
{
    __shared__ float As[2][128][20];
    __shared__ float Bs[2][16][132];
    __shared__ float scol[128], ssq[128];

    const int t = threadIdx.x;
    const int lane = t & 31, warp = t >> 5;
    const int g = lane >> 2, tg = lane & 3;
    const int warpM = warp >> 2, warpN = warp & 3;   // 2 x 4 warps
    const int m0 = blockIdx.y * 128, n0 = blockIdx.x * 128;

    float acc[4][4][4];
    #pragma unroll
    for (int mt=0; mt<4; mt++)
        #pragma unroll
        for (int nt=0; nt<4; nt++)
            #pragma unroll
            for (int i=0; i<4; i++) acc[mt][nt][i] = 0.f;

    const int ntiles = K >> 4;

    const int a0m = t >> 2,        a0k = t & 3;
    const int a1m = (t+256) >> 2;
    const int b0k = t >> 5,        b0n = (t & 31) * 4;
    const int b1k = (t+256) >> 5;

    {
        bool p0 = (m0 + a0m) < M, p1 = (m0 + a1m) < M;
        cpa16(&As[0][a0m][a0k*4], A + (size_t)(m0+a0m)*K + a0k*4, p0);
        cpa16(&As[0][a1m][a0k*4], A + (size_t)(m0+a1m)*K + a0k*4, p1);
        cpa16(&Bs[0][b0k][b0n],   B + (size_t)b0k*N + n0 + b0n, true);
        cpa16(&Bs[0][b1k][b0n],   B + (size_t)b1k*N + n0 + b0n, true);
    }
    cpa_commit();

    for (int kt = 0; kt < ntiles; kt++) {
        const int cur = kt & 1;
        if (kt + 1 < ntiles) {
            const int nxt = (kt+1) & 1;
            const int k0 = (kt+1) << 4;
            bool p0 = (m0 + a0m) < M, p1 = (m0 + a1m) < M;
            cpa16(&As[nxt][a0m][a0k*4], A + (size_t)(m0+a0m)*K + k0 + a0k*4, p0);
            cpa16(&As[nxt][a1m][a0k*4], A + (size_t)(m0+a1m)*K + k0 + a0k*4, p1);
            cpa16(&Bs[nxt][b0k][b0n],   B + (size_t)(k0+b0k)*N + n0 + b0n, true);
            cpa16(&Bs[nxt][b1k][b0n],   B + (size_t)(k0+b1k)*N + n0 + b0n, true);
            cpa_commit();
            cpa_wait<1>();
        } else {
            cpa_commit();
            cpa_wait<0>();
        }
        __syncthreads();

        uint32_t ah[4][4], al[4][4], bh[4][2], bl[4][2];
        #pragma unroll
        for (int mt = 0; mt < 4; mt++) {
            const int mr = warpM*64 + mt*16;
            float2 p0 = *(const float2*)&As[cur][mr+g  ][2*tg  ];
            float2 p1 = *(const float2*)&As[cur][mr+g+8][2*tg  ];
            float2 p2 = *(const float2*)&As[cur][mr+g  ][2*tg+8];
            float2 p3 = *(const float2*)&As[cur][mr+g+8][2*tg+8];
            split2(p0.x, p0.y, ah[mt][0], al[mt][0]);
            split2(p1.x, p1.y, ah[mt][1], al[mt][1]);
            split2(p2.x, p2.y, ah[mt][2], al[mt][2]);
            split2(p3.x, p3.y, ah[mt][3], al[mt][3]);
        }
        #pragma unroll
        for (int nt = 0; nt < 4; nt++) {
            const int nc = warpN*32 + nt*8 + g;
            float q0 = Bs[cur][2*tg  ][nc];
            float q1 = Bs[cur][2*tg+1][nc];
            float q2 = Bs[cur][2*tg+8][nc];
            float q3 = Bs[cur][2*tg+9][nc];
            split2(q0, q1, bh[nt][0], bl[nt][0]);
            split2(q2, q3, bh[nt][1], bl[nt][1]);
        }
        #pragma unroll
        for (int mt = 0; mt < 4; mt++)
            #pragma unroll
            for (int nt = 0; nt < 4; nt++) {
                mma_bf16(acc[mt][nt], al[mt], bh[nt]);
                mma_bf16(acc[mt][nt], ah[mt], bl[nt]);
                mma_bf16(acc[mt][nt], ah[mt], bh[nt]);
            }
        __syncthreads();
    }

    float colsum[8], colsq[8];
    if (FUSED) {
        #pragma unroll
        for (int j=0;j<8;j++){ colsum[j]=0.f; colsq[j]=0.f; }
        if (t < 128) { scol[t]=0.f; ssq[t]=0.f; }
        __syncthreads();
    }

    #pragma unroll
    for (int mt = 0; mt < 4; mt++) {
        const int r0 = m0 + warpM*64 + mt*16 + g;
        #pragma unroll
        for (int nt = 0; nt < 4; nt++) {
            const int col = n0 + warpN*32 + nt*8 + tg*2;
            float2 v0 = make_float2(acc[mt][nt][0], acc[mt][nt][1]);
            float2 v1 = make_float2(acc[mt][nt][2], acc[mt][nt][3]);
            if (FUSED) {
                float b0 = bias[col], b1 = bias[col+1];
                v0.x = fmaxf(v0.x + b0, 0.f); v0.y = fmaxf(v0.y + b1, 0.f);
                v1.x = fmaxf(v1.x + b0, 0.f); v1.y = fmaxf(v1.y + b1, 0.f);
                if (r0 < M) {
                    colsum[nt*2]   += v0.x; colsq[nt*2]   += v0.x*v0.x;
                    colsum[nt*2+1] += v0.y; colsq[nt*2+1] += v0.y*v0.y;
                }
                if (r0 + 8 < M) {
                    colsum[nt*2]   += v1.x; colsq[nt*2]   += v1.x*v1.x;
                    colsum[nt*2+1] += v1.y; colsq[nt*2+1] += v1.y*v1.y;
                }
            }
            if (r0 < M)     *(float2*)&C[(size_t)r0*N + col]     = v0;
            if (r0 + 8 < M) *(float2*)&C[(size_t)(r0+8)*N + col] = v1;
        }
    }

    if (FUSED) {
        #pragma unroll
        for (int j = 0; j < 8; j++) {
            float s = colsum[j], q = colsq[j];
            s += __shfl_down_sync(0xffffffff, s, 16); q += __shfl_down_sync(0xffffffff, q, 16);
            s += __shfl_down_sync(0xffffffff, s, 8);  q += __shfl_down_sync(0xffffffff, q, 8);
            s += __shfl_down_sync(0xffffffff, s, 4);  q += __shfl_down_sync(0xffffffff, q, 4);
            if (lane < 4) {
                int col = warpN*32 + (j>>1)*8 + lane*2 + (j&1);
                atomicAdd(&scol[col], s);
                atomicAdd(&ssq[col], q);
            }
        }
        __syncthreads();
        if (t < 128) {
            part[(size_t)blockIdx.y*256 + t]       = scol[t];
            part[(size_t)blockIdx.y*256 + 128 + t] = ssq[t];
        }
    }
}

__global__ void bn_finalize2(const float* __restrict__ part, int nb,
                             const float* g, const float* beta,
                             float M, float* scale, float* shift)
{
    int c = threadIdx.x;  // 128
    float s1 = 0.f, s2 = 0.f;
    for (int b = 0; b < nb; b++) {
        s1 += part[b*256 + c];
        s2 += part[b*256 + 128 + c];
    }
    float mu  = s1 / M;
    float var = s2 / M - mu*mu;
    float inv = rsqrtf(var + 1e-5f);
    scale[c] = g[c]*inv;
    shift[c] = beta[c] - mu*g[c]*inv;
}

// ---------------- fused BN-apply + logits GEMV ----------------
__global__ __launch_bounds__(256)
void bn_apply_gemv(const float* __restrict__ H, const float* __restrict__ scale,
                   const float* __restrict__ shift, const float* __restrict__ wt,
                   float* __restrict__ out, float* __restrict__ l, int N)
{
    __shared__ float swt[512], ssc[128], ssh[128];
    int t = threadIdx.x;
    if (t < 128) {
        *(float4*)&swt[t*4] = *(const float4*)&wt[t*4];
        ssc[t] = scale[t]; ssh[t] = shift[t];
    }
    __syncthreads();
    int warp = t >> 5, lane = t & 31;
    int row = blockIdx.x*8 + warp;
    if (row >= N) return;
    float4 hv = *(const float4*)&H[(size_t)row*128 + lane*4];
    float4 ov;
    ov.x = hv.x*ssc[lane*4+0] + ssh[lane*4+0];
    ov.y = hv.y*ssc[lane*4+1] + ssh[lane*4+1];
    ov.z = hv.z*ssc[lane*4+2] + ssh[lane*4+2];
    ov.w = hv.w*ssc[lane*4+3] + ssh[lane*4+3];
    *(float4*)&out[(size_t)row*128 + lane*4] = ov;
    float s0=0.f, s1=0.f, s2=0.f, s3=0.f;
    #pragma unroll
    for (int j = 0; j < 4; j++) {
        float xj = j==0?ov.x : j==1?ov.y : j==2?ov.z : ov.w;
        float4 w = *(const float4*)&swt[(lane*4+j)*4];
        s0 += xj*w.x; s1 += xj*w.y; s2 += xj*w.z; s3 += xj*w.w;
    }
    #pragma unroll
    for (int off=16; off; off>>=1) {
        s0 += __shfl_down_sync(0xffffffff, s0, off);
        s1 += __shfl_down_sync(0xffffffff, s1, off);
        s2 += __shfl_down_sync(0xffffffff, s2, off);
        s3 += __shfl_down_sync(0xffffffff, s3, off);
    }
    if (!lane) *(float4*)&l[(size_t)row*4] = make_float4(s0, s1, s2, s3);
}

// ---------------- attention-vector folds (all 4 in one launch) ----------------
__global__ void att_vec_all(const float* W1, const float* a1, float* o1,
                            const float* W2, const float* a2, float* o2,
                            const float* W3, const float* a3, float* o3,
                            const float* W4, const float* a4, float* o4)
{
    const float* W; const float* a; float* o;
    switch (blockIdx.x) {
        case 0: W=W1; a=a1; o=o1; break;
        case 1: W=W2; a=a2; o=o2; break;
        case 2: W=W3; a=a3; o=o3; break;
        default: W=W4; a=a4; o=o4; break;
    }
    __shared__ float sa[512];
    int t = threadIdx.x;            // 128
    *(float4*)&sa[t*4] = *(const float4*)&a[t*4];
    __syncthreads();
    float s0=0.f, s1=0.f, s2=0.f, s3=0.f;
    const float* Wr = W + (size_t)t*512;
    #pragma unroll 4
    for (int c = 0; c < 128; c++) {
        s0 += Wr[c]     * sa[c];
        s1 += Wr[128+c] * sa[128+c];
        s2 += Wr[256+c] * sa[256+c];
        s3 += Wr[384+c] * sa[384+c];
    }
    *(float4*)&o[t*4] = make_float4(s0, s1, s2, s3);
}

// ---------------- CSR build: both relations fused ----------------
__global__ void edge_count_both(const int* __restrict__ s1, const int* __restrict__ d1,
                                int E1, int nl1, int* c1,
                                const int* __restrict__ s2, const int* __restrict__ d2,
                                int E2, int nl2, int* c2)
{
    int i = blockIdx.x*blockDim.x + threadIdx.x;
    int T1 = E1 + nl1;
    int T  = T1 + E2 + nl2;
    if (i < T1) {
        int d;
        if (i < E1) { int s = s1[i]; d = d1[i]; if (s == d) return; }
        else d = i - E1;
        atomicAdd(&c1[d], 1);
    } else if (i < T) {
        int j = i - T1;
        int d;
        if (j < E2) { int s = s2[j]; d = d2[j]; if (s == d) return; }
        else d = j - E2;
        atomicAdd(&c2[d], 1);
    }
}

__global__ void edge_scatter_both(const int* __restrict__ s1, const int* __restrict__ d1,
                                  int E1, int nl1, int* w1, int* el1,
                                  const int* __restrict__ s2, const int* __restrict__ d2,
                                  int E2, int nl2, int* w2, int* el2)
{
    int i = blockIdx.x*blockDim.x + threadIdx.x;
    int T1 = E1 + nl1;
    int T  = T1 + E2 + nl2;
    if (i < T1) {
        int s, d;
        if (i < E1) { s = s1[i]; d = d1[i]; if (s == d) return; }
        else { d = i - E1; s = d; }
        int pos = atomicAdd(&w1[d], 1);
        el1[pos] = s;
    } else if (i < T) {
        int j = i - T1;
        int s, d;
        if (j < E2) { s = s2[j]; d = d2[j]; if (s == d) return; }
        else { d = j - E2; s = d; }
        int pos = atomicAdd(&w2[d], 1);
        el2[pos] = s;
    }
}

// tile-based exclusive scan, both relations in one launch (block 0 / block 1)
__global__ __launch_bounds__(1024)
void exscan_both(const int* __restrict__ c1, int* __restrict__ r1, int* __restrict__ w1, int n1,
                 const int* __restrict__ c2, int* __restrict__ r2, int* __restrict__ w2, int n2)
{
    const int* cnt; int* rowptr; int* wptr; int n;
    if (blockIdx.x == 0) { cnt=c1; rowptr=r1; wptr=w1; n=n1; }
    else                 { cnt=c2; rowptr=r2; wptr=w2; n=n2; }

    __shared__ int warpsum[32];
    int t = threadIdx.x, lane = t & 31, wid = t >> 5;
    int running = 0;
    for (int base = 0; base < n; base += 1024) {
        int i = base + t;
        int v = (i < n) ? cnt[i] : 0;
        int inc = v;
        #pragma unroll
        for (int off=1; off<32; off<<=1) {
            int u = __shfl_up_sync(0xffffffff, inc, off);
            if (lane >= off) inc += u;
        }
        if (lane == 31) warpsum[wid] = inc;
        __syncthreads();
        if (wid == 0) {
            int s = warpsum[lane];
            #pragma unroll
            for (int off=1; off<32; off<<=1) {
                int u = __shfl_up_sync(0xffffffff, s, off);
                if (lane >= off) s += u;
            }
            warpsum[lane] = s;
        }
        __syncthreads();
        int wbase = wid ? warpsum[wid-1] : 0;
        int total = warpsum[31];
        int excl = running + wbase + (inc - v);
        if (i < n) { rowptr[i] = excl; wptr[i] = excl; }
        running += total;
        __syncthreads();
    }
    if (t == 0) rowptr[n] = running;
}

// ---------------- per-dst softmax + gather aggregation (+optional fused logits) ----------------
__global__ __launch_bounds__(128)
void gat_aggregate(const float* __restrict__ xs, const float* __restrict__ ls,
                   const float* __restrict__ ld,
                   const int* __restrict__ rowptr, const int* __restrict__ elist,
                   const float* __restrict__ base, const float* __restrict__ bias,
                   float* __restrict__ out,
                   const float* __restrict__ nwts, const float* __restrict__ nwtd,
                   float* __restrict__ lsout, float* __restrict__ ldout)
{
    int d = blockIdx.x;
    int c = threadIdx.x;  // 128 threads
    int h = c >> 5, lane = c & 31;
    int e0 = rowptr[d], e1 = rowptr[d+1];

    __shared__ float sm[4], sdinv[4], sldv[4];
    __shared__ float w[128*4];
    __shared__ int   ssrc[128];
    __shared__ float sws[512], swd[512], sv[128];

    if (lsout) {
        *(float4*)&sws[c*4] = *(const float4*)&nwts[c*4];
        *(float4*)&swd[c*4] = *(const float4*)&nwtd[c*4];
    }

    // warp h computes softmax stats for head h, lanes parallel over edges
    {
        float ldh = ld[(size_t)d*4 + h];
        float mx = -3.0e38f;
        for (int e = e0 + lane; e < e1; e += 32) {
            int s = elist[e];
            float x = ls[(size_t)s*4 + h] + ldh;
            x = (x > 0.f) ? x : 0.2f*x;
            mx = fmaxf(mx, x);
        }
        #pragma unroll
        for (int off=16; off; off>>=1) mx = fmaxf(mx, __shfl_xor_sync(0xffffffff, mx, off));
        float den = 0.f;
        for (int e = e0 + lane; e < e1; e += 32) {
            int s = elist[e];
            float x = ls[(size_t)s*4 + h] + ldh;
            x = (x > 0.f) ? x : 0.2f*x;
            den += __expf(x - mx);
        }
        #pragma unroll
        for (int off=16; off; off>>=1) den += __shfl_xor_sync(0xffffffff, den, off);
        if (!lane) {
            sm[h] = mx;
            sdinv[h] = (e1 > e0) ? (1.f/den) : 0.f;
            sldv[h] = ldh;
        }
    }
    __syncthreads();

    float a0=0.f, a1=0.f, a2=0.f, a3=0.f;
    for (int eb=e0; eb<e1; eb+=128) {
        int ne = min(128, e1-eb);
        if (c < ne) ssrc[c] = elist[eb + c];
        __syncthreads();
        for (int t=c; t < ne*4; t += 128) {
            int e = t >> 2, hh = t & 3;
            int s = ssrc[e];
            float x = ls[(size_t)s*4 + hh] + sldv[hh];
            x = (x > 0.f) ? x : 0.2f*x;
            w[t] = __expf(x - sm[hh]) * sdinv[hh];
        }
        __syncthreads();
        for (int e=0; e<ne; e++) {
            const float* xr = xs + (size_t)ssrc[e]*512;
            float4 ww = *(const float4*)&w[e*4];
            a0 += ww.x * xr[c];
            a1 += ww.y * xr[128+c];
            a2 += ww.z * xr[256+c];
            a3 += ww.w * xr[384+c];
        }
        __syncthreads();
    }
    size_t oi = (size_t)d*128 + c;
    float v = base[oi] + 0.25f*(a0+a1+a2+a3) + bias[c];
    out[oi] = v;

    if (lsout) {
        sv[c] = v;
        __syncthreads();
        if (c < 32) {
            float ps[4] = {0,0,0,0}, pd[4] = {0,0,0,0};
            #pragma unroll
            for (int j = 0; j < 4; j++) {
                int cc = c + j*32;
                float vv = sv[cc];
                #pragma unroll
                for (int hh = 0; hh < 4; hh++) {
                    ps[hh] += vv * sws[cc*4 + hh];
                    pd[hh] += vv * swd[cc*4 + hh];
                }
            }
            #pragma unroll
            for (int off=16; off; off>>=1) {
                #pragma unroll
                for (int hh = 0; hh < 4; hh++) {
                    ps[hh] += __shfl_down_sync(0xffffffff, ps[hh], off);
                    pd[hh] += __shfl_down_sync(0xffffffff, pd[hh], off);
                }
            }
            if (c == 0) {
                *(float4*)&lsout[(size_t)d*4] = make_float4(ps[0], ps[1], ps[2], ps[3]);
                *(float4*)&ldout[(size_t)d*4] = make_float4(pd[0], pd[1], pd[2], pd[3]);
            }
        }
    }
}

// ---------------- launch ----------------
extern "C" void kernel_launch(void* const* d_in, const int* in_sizes, int n_in,
                              void* d_out, int out_size)
{
    const float* x_gene = (const float*)d_in[0];
    const float* x_dis  = (const float*)d_in[1];
    const int*   e1s    = (const int*)d_in[2];
    const int*   e1d    = (const int*)d_in[3];
    const int*   e2s    = (const int*)d_in[4];
    const int*   e2d    = (const int*)d_in[5];
    const float* Wg    = (const float*)d_in[6];
    const float* bg    = (const float*)d_in[7];
    const float* gg    = (const float*)d_in[8];
    const float* betag = (const float*)d_in[9];
    const float* Wd    = (const float*)d_in[10];
    const float* bd    = (const float*)d_in[11];
    const float* gd    = (const float*)d_in[12];
    const float* betad = (const float*)d_in[13];
    const float* W1s = (const float*)d_in[14];
    const float* W1d = (const float*)d_in[15];
    const float* a1s = (const float*)d_in[16];
    const float* a1d = (const float*)d_in[17];
    const float* b1  = (const float*)d_in[18];
    const float* W2s = (const float*)d_in[19];
    const float* W2d = (const float*)d_in[20];
    const float* a2s = (const float*)d_in[21];
    const float* a2d = (const float*)d_in[22];
    const float* b2  = (const float*)d_in[23];

    float *Hg,*Hd,*gene,*xs,*ls1,*ld1,*ls2,*ld2,*partg,*partd;
    float *scaleg,*shiftg,*scaled,*shiftd,*wts1,*wtd1,*wts2,*wtd2;
    int *cnt1,*cnt2,*rowptr1,*rowptr2,*wptr1,*wptr2,*elist1,*elist2;
    cudaGetSymbolAddress((void**)&Hg,    g_Hg);
    cudaGetSymbolAddress((void**)&Hd,    g_Hd);
    cudaGetSymbolAddress((void**)&gene,  g_gene);
    cudaGetSymbolAddress((void**)&xs,    g_xs);
    cudaGetSymbolAddress((void**)&ls1,   g_ls1);
    cudaGetSymbolAddress((void**)&ld1,   g_ld1);
    cudaGetSymbolAddress((void**)&ls2,   g_ls2);
    cudaGetSymbolAddress((void**)&ld2,   g_ld2);
    cudaGetSymbolAddress((void**)&partg, g_partg);
    cudaGetSymbolAddress((void**)&partd, g_partd);
    cudaGetSymbolAddress((void**)&scaleg,g_scaleg);
    cudaGetSymbolAddress((void**)&shiftg,g_shiftg);
    cudaGetSymbolAddress((void**)&scaled,g_scaled);
    cudaGetSymbolAddress((void**)&shiftd,g_shiftd);
    cudaGetSymbolAddress((void**)&wts1,  g_wts1);
    cudaGetSymbolAddress((void**)&wtd1,  g_wtd1);
    cudaGetSymbolAddress((void**)&wts2,  g_wts2);
    cudaGetSymbolAddress((void**)&wtd2,  g_wtd2);
    cudaGetSymbolAddress((void**)&cnt1,  g_cnt1);
    cudaGetSymbolAddress((void**)&cnt2,  g_cnt2);
    cudaGetSymbolAddress((void**)&rowptr1,g_rowptr1);
    cudaGetSymbolAddress((void**)&rowptr2,g_rowptr2);
    cudaGetSymbolAddress((void**)&wptr1, g_wptr1);
    cudaGetSymbolAddress((void**)&wptr2, g_wptr2);
    cudaGetSymbolAddress((void**)&elist1,g_elist1);
    cudaGetSymbolAddress((void**)&elist2,g_elist2);

    float* out_gene = (float*)d_out;
    float* out_dis  = (float*)d_out + (size_t)NGENE*CDIM;

    cudaStream_t sB = g_ctx.sB, sC = g_ctx.sC;

    // fork
    cudaEventRecord(g_ctx.ev0, 0);
    cudaStreamWaitEvent(sB, g_ctx.ev0, 0);
    cudaStreamWaitEvent(sC, g_ctx.ev0, 0);

    // ---- stream C: attention-vector folds + CSR builds (feature-independent) ----
    att_vec_all<<<4,128,0,sC>>>(W1s,a1s,wts1, W1d,a1d,wtd1, W2s,a2s,wts2, W2d,a2d,wtd2);
    cudaEventRecord(g_ctx.evC0, sC);
    zero2_i<<<(NGENE+255)/256,256,0,sC>>>(cnt1, cnt2, NGENE);
    {
        int tot = (E1N+NDIS) + (E2N+NGENE);
        edge_count_both<<<(tot+255)/256,256,0,sC>>>(e1s,e1d,E1N,NDIS,cnt1,
                                                    e2s,e2d,E2N,NGENE,cnt2);
        exscan_both<<<2,1024,0,sC>>>(cnt1,rowptr1,wptr1,NGENE, cnt2,rowptr2,wptr2,NGENE);
        edge_scatter_both<<<(tot+255)/256,256,0,sC>>>(e1s,e1d,E1N,NDIS,wptr1,elist1,
                                                      e2s,e2d,E2N,NGENE,wptr2,elist2);
    }
    cudaEventRecord(g_ctx.evCsr, sC);

    // ---- stream B: dis encoder -> BN(+ls1 gemv) -> xs1 GEMM ----
    tgemm<1><<<dim3(1, NBD), 256, 0, sB>>>(x_dis, Wd, bd, Hd, NDIS, 128, 256, partd);
    bn_finalize2<<<1,128,0,sB>>>(partd, NBD, gd, betad, (float)NDIS, scaled, shiftd);
    cudaStreamWaitEvent(sB, g_ctx.evC0, 0);
    bn_apply_gemv<<<(NDIS+7)/8,256,0,sB>>>(Hd, scaled, shiftd, wts1, out_dis, ls1, NDIS);
    tgemm<0><<<dim3(4, NBD), 256, 0, sB>>>(out_dis, W1s, nullptr, xs, NDIS, 512, 128, nullptr);
    cudaEventRecord(g_ctx.evB, sB);

    // ---- stream 0 (main): gene encoder -> BN(+ld1 gemv) -> agg1 -> xs2 -> agg2 ----
    tgemm<1><<<dim3(1, NBG), 256>>>(x_gene, Wg, bg, Hg, NGENE, 128, 512, partg);
    bn_finalize2<<<1,128>>>(partg, NBG, gg, betag, (float)NGENE, scaleg, shiftg);
    cudaStreamWaitEvent(0, g_ctx.evC0, 0);
    bn_apply_gemv<<<(NGENE+7)/8,256>>>(Hg, scaleg, shiftg, wtd1, gene, ld1, NGENE);
    cudaStreamWaitEvent(0, g_ctx.evB, 0);
    cudaStreamWaitEvent(0, g_ctx.evCsr, 0);
    gat_aggregate<<<NGENE,128>>>(xs, ls1, ld1, rowptr1, elist1, gene, b1, gene,
                                 wts2, wtd2, ls2, ld2);
    tgemm<0><<<dim3(4, NBG), 256>>>(gene, W2s, nullptr, xs, NGENE, 512, 128, nullptr);
    gat_aggregate<<<NGENE,128>>>(xs, ls2, ld2, rowptr2, elist2, gene, b2, out_gene,
                                 nullptr, nullptr, nullptr, nullptr);
}